// round 1
// baseline (speedup 1.0000x reference)
#include <cuda_runtime.h>
#include <math.h>

// TemporalAttentionEncoder — restructured:
//   e_mean = mean_S(x) + pe_mean ; q_mean = e_mean@w_q+b_q ; q_hat = q_mean@w2+b2
//   r[b,h,:] = w_k[:, h*32:(h+1)*32] @ q_hat[b,h,:]   (b_k cancels under softmax)
//   scores[b,h,s] = (e_p[b,s] . r[b,h]) / sqrt(32) ; probs = softmax_s
//   attn[b, h*128+d] = sum_s probs[b,h,s] * e_p[(4b+h) mod B, s, d]   (torch tile quirk)
//   out = relu(( relu((attn@w3a+b3a)*g3a+be3a) @ w3b + b3b)*g3b + be3b)

#define B_   4096
#define S_   64
#define D_   128
#define H_   4
#define MB   8      // batches per block in kQR
#define MBE  16     // batches per block in kMLP

// Scratch (static device globals — no allocation in kernel_launch)
__device__ float g_pe[S_ * D_];          // 32 KB positional encoding table
__device__ float g_wkT[D_ * D_];         // 64 KB w_k transposed: g_wkT[c*128+d] = w_k[d*128+c]
__device__ float g_r[(size_t)B_ * H_ * D_];     // 8 MB
__device__ float g_probs[(size_t)B_ * H_ * S_]; // 4 MB
__device__ float g_attn[(size_t)B_ * H_ * D_];  // 8 MB

// ---------------------------------------------------------------------------
// Positional encoding table: pe[s, 2i] = sin(s/1000^(i/64)), pe[s,2i+1] = cos(...)
__global__ void kPE() {
    int s = blockIdx.x;
    int t = threadIdx.x;
    int i = t >> 1;
    float freq = powf(1000.0f, -(float)i / 64.0f);
    float a = (float)s * freq;
    g_pe[s * D_ + t] = (t & 1) ? cosf(a) : sinf(a);
}

// ---------------------------------------------------------------------------
// One-time transpose of w_k (64 KB; read coalesced, scattered write is fine)
__global__ void kT(const float* __restrict__ w_k) {
    int t = threadIdx.x;
    for (int row = 0; row < D_; row++)
        g_wkT[t * D_ + row] = w_k[row * D_ + t];
}

// ---------------------------------------------------------------------------
// Fused chain: e_mean -> q_mean -> q_hat -> r.  Block = 128 threads (thread = output dim),
// MB batches per block. Weights read coalesced from global (L2-resident, 128 KB total).
__global__ void kQR(const float* __restrict__ x,
                    const float* __restrict__ w_q, const float* __restrict__ b_q,
                    const float* __restrict__ w2,  const float* __restrict__ b2) {
    __shared__ float em_s[MB * D_];
    __shared__ float qm_s[MB * D_];
    __shared__ float qh_s[MB * D_];
    int t = threadIdx.x;
    int b0 = blockIdx.x * MB;

    // pe_mean for this output dim
    float pm = 0.f;
    #pragma unroll 8
    for (int s = 0; s < S_; s++) pm += g_pe[s * D_ + t];
    pm *= (1.0f / (float)S_);

    // e_mean per batch (reads x, coalesced)
    for (int m = 0; m < MB; m++) {
        const float* xp = x + (size_t)(b0 + m) * S_ * D_ + t;
        float acc = 0.f;
        #pragma unroll
        for (int s = 0; s < S_; s++) acc += xp[s * D_];
        em_s[m * D_ + t] = acc * (1.0f / (float)S_) + pm;
    }
    __syncthreads();

    // q_mean = e_mean @ w_q + b_q
    {
        float acc[MB];
        #pragma unroll
        for (int m = 0; m < MB; m++) acc[m] = 0.f;
        for (int i = 0; i < D_; i++) {
            float wv = w_q[i * D_ + t];
            #pragma unroll
            for (int m = 0; m < MB; m++) acc[m] += em_s[m * D_ + i] * wv;
        }
        float bq = b_q[t];
        #pragma unroll
        for (int m = 0; m < MB; m++) qm_s[m * D_ + t] = acc[m] + bq;
    }
    __syncthreads();

    // q_hat = q_mean @ w2 + b2
    {
        float acc[MB];
        #pragma unroll
        for (int m = 0; m < MB; m++) acc[m] = 0.f;
        for (int i = 0; i < D_; i++) {
            float wv = w2[i * D_ + t];
            #pragma unroll
            for (int m = 0; m < MB; m++) acc[m] += qm_s[m * D_ + i] * wv;
        }
        float bb = b2[t];
        #pragma unroll
        for (int m = 0; m < MB; m++) qh_s[m * D_ + t] = acc[m] + bb;
    }
    __syncthreads();

    // r[b,h,d] = sum_{j<32} w_k[d, h*32+j] * q_hat[b, h*32+j]  (via transposed w_k)
    for (int h = 0; h < H_; h++) {
        float acc[MB];
        #pragma unroll
        for (int m = 0; m < MB; m++) acc[m] = 0.f;
        #pragma unroll 8
        for (int j = 0; j < 32; j++) {
            int c = h * 32 + j;
            float wv = g_wkT[c * D_ + t];
            #pragma unroll
            for (int m = 0; m < MB; m++) acc[m] += qh_s[m * D_ + c] * wv;
        }
        #pragma unroll
        for (int m = 0; m < MB; m++)
            g_r[((size_t)(b0 + m) * H_ + h) * D_ + t] = acc[m];
    }
}

// ---------------------------------------------------------------------------
// scores + softmax -> probs.  Block per batch b, 128 threads.
// e_p staged in smem with +1 pad (row stride 129) for conflict-free column dots.
__global__ void kProbs(const float* __restrict__ x) {
    __shared__ float ep[S_ * (D_ + 1)];
    __shared__ float rs[H_ * D_];
    __shared__ float sc[H_ * S_];
    int t = threadIdx.x;
    int b = blockIdx.x;

    const float* xb = x + (size_t)b * S_ * D_;
    for (int s = 0; s < S_; s++)
        ep[s * (D_ + 1) + t] = xb[s * D_ + t] + g_pe[s * D_ + t];
    #pragma unroll
    for (int q = 0; q < H_; q++)
        rs[q * D_ + t] = g_r[((size_t)b * H_ + q) * D_ + t];
    __syncthreads();

    const float scale = 0.17677669529663689f;  // 1/sqrt(32)
    #pragma unroll
    for (int p = 0; p < 2; p++) {
        int idx = p * 128 + t;
        int h = idx >> 6, s = idx & 63;
        float acc = 0.f;
        #pragma unroll 16
        for (int d = 0; d < D_; d++) acc += ep[s * (D_ + 1) + d] * rs[h * D_ + d];
        sc[idx] = acc * scale;
    }
    __syncthreads();

    // softmax over s (64 entries): warp w handles head h=w, each lane owns 2 entries
    int h = t >> 5, l = t & 31;
    float v0 = sc[h * 64 + l];
    float v1 = sc[h * 64 + 32 + l];
    float mx = fmaxf(v0, v1);
    #pragma unroll
    for (int o = 16; o > 0; o >>= 1) mx = fmaxf(mx, __shfl_xor_sync(0xffffffffu, mx, o));
    float e0 = expf(v0 - mx), e1 = expf(v1 - mx);
    float sum = e0 + e1;
    #pragma unroll
    for (int o = 16; o > 0; o >>= 1) sum += __shfl_xor_sync(0xffffffffu, sum, o);
    float inv = 1.0f / sum;
    float* pp = g_probs + ((size_t)b * H_ + h) * S_;
    pp[l] = e0 * inv;
    pp[32 + l] = e1 * inv;
}

// ---------------------------------------------------------------------------
// attn: block per SOURCE batch j; serves its 4 consumers (b=(j>>2)+1024k, h=j&3).
__global__ void kAttn(const float* __restrict__ x) {
    __shared__ float ep[S_ * D_];
    __shared__ float pr[4 * S_];
    int t = threadIdx.x;
    int j = blockIdx.x;

    const float* xj = x + (size_t)j * S_ * D_;
    for (int s = 0; s < S_; s++)
        ep[s * D_ + t] = xj[s * D_ + t] + g_pe[s * D_ + t];

    int h = j & 3;
    int bbase = j >> 2;
    if (t < S_) {
        #pragma unroll
        for (int k = 0; k < 4; k++) {
            int b = bbase + 1024 * k;
            pr[k * S_ + t] = g_probs[((size_t)b * H_ + h) * S_ + t];
        }
    }
    __syncthreads();

    #pragma unroll
    for (int k = 0; k < 4; k++) {
        float acc = 0.f;
        #pragma unroll 16
        for (int s = 0; s < S_; s++) acc += pr[k * S_ + s] * ep[s * D_ + t];
        int b = bbase + 1024 * k;
        g_attn[(size_t)b * (H_ * D_) + h * D_ + t] = acc;
    }
}

// ---------------------------------------------------------------------------
// MLP: (B,512)@(512,128) +BN+ReLU -> (B,128)@(128,128) +BN+ReLU.
// 16 batches per block amortize the weight stream (L2-resident).
__global__ void kMLP(const float* __restrict__ w3a, const float* __restrict__ b3a,
                     const float* __restrict__ g3a, const float* __restrict__ be3a,
                     const float* __restrict__ w3b, const float* __restrict__ b3b,
                     const float* __restrict__ g3b, const float* __restrict__ be3b,
                     float* __restrict__ out) {
    __shared__ float as[MBE * 512];
    __shared__ float h1[MBE * D_];
    int t = threadIdx.x;
    int b0 = blockIdx.x * MBE;

    const float* ap = g_attn + (size_t)b0 * 512;
    for (int i = t; i < MBE * 512; i += 128) as[i] = ap[i];
    __syncthreads();

    float acc[MBE];
    #pragma unroll
    for (int m = 0; m < MBE; m++) acc[m] = 0.f;
    for (int i = 0; i < 512; i++) {
        float wv = w3a[i * D_ + t];
        #pragma unroll
        for (int m = 0; m < MBE; m++) acc[m] += as[m * 512 + i] * wv;
    }
    {
        float bb = b3a[t], gg = g3a[t], be = be3a[t];
        #pragma unroll
        for (int m = 0; m < MBE; m++) {
            float v = (acc[m] + bb) * gg + be;
            h1[m * D_ + t] = fmaxf(v, 0.f);
        }
    }
    __syncthreads();

    #pragma unroll
    for (int m = 0; m < MBE; m++) acc[m] = 0.f;
    for (int i = 0; i < D_; i++) {
        float wv = w3b[i * D_ + t];
        #pragma unroll
        for (int m = 0; m < MBE; m++) acc[m] += h1[m * D_ + i] * wv;
    }
    {
        float bb = b3b[t], gg = g3b[t], be = be3b[t];
        #pragma unroll
        for (int m = 0; m < MBE; m++) {
            float v = (acc[m] + bb) * gg + be;
            out[(size_t)(b0 + m) * D_ + t] = fmaxf(v, 0.f);
        }
    }
}

// ---------------------------------------------------------------------------
extern "C" void kernel_launch(void* const* d_in, const int* in_sizes, int n_in,
                              void* d_out, int out_size) {
    const float* x    = (const float*)d_in[0];
    const float* w_q  = (const float*)d_in[1];
    const float* b_q  = (const float*)d_in[2];
    const float* w_k  = (const float*)d_in[3];
    // d_in[4] = b_k: provably cancels in softmax (constant shift over s) — unused.
    const float* w2   = (const float*)d_in[5];
    const float* b2   = (const float*)d_in[6];
    const float* w3a  = (const float*)d_in[7];
    const float* b3a  = (const float*)d_in[8];
    const float* g3a  = (const float*)d_in[9];
    const float* be3a = (const float*)d_in[10];
    const float* w3b  = (const float*)d_in[11];
    const float* b3b  = (const float*)d_in[12];
    const float* g3b  = (const float*)d_in[13];
    const float* be3b = (const float*)d_in[14];
    float* out = (float*)d_out;

    kPE  <<<S_, D_>>>();
    kT   <<<1, D_>>>(w_k);
    kQR  <<<B_ / MB, D_>>>(x, w_q, b_q, w2, b2);
    kProbs<<<B_, D_>>>(x);
    kAttn<<<B_, D_>>>(x);
    kMLP <<<B_ / MBE, D_>>>(w3a, b3a, g3a, be3a, w3b, b3b, g3b, be3b, out);
}

// round 2
// speedup vs baseline: 1.1267x; 1.1267x over previous
#include <cuda_runtime.h>
#include <math.h>

// TemporalAttentionEncoder — fused group formulation.
// Group i in [0,1024): consumers b = i+1024k (k=0..3); attn[b,h] sources x[4i+h].
// Per-group block does: e_mean (4 consumers) -> q chain -> r -> scores+softmax
// (consumer tiles re-read, L2-hot) -> attention over the 4 source tiles.
// Then a separate MLP kernel. x is read from DRAM exactly twice in total.

#define B_   4096
#define S_   64
#define D_   128
#define H_   4
#define MBE  16

__device__ float g_pe[S_ * D_];       // positional encoding table (32 KB)
__device__ float g_pem[D_];           // column mean of pe
__device__ float g_wkT[D_ * D_];      // w_k transposed: g_wkT[c*128+d] = w_k[d*128+c]
__device__ float g_attn[(size_t)B_ * H_ * D_];  // 8 MB

// ---------------------------------------------------------------------------
__global__ void kPE() {
    int s = blockIdx.x, t = threadIdx.x;
    int i = t >> 1;
    float freq = powf(1000.0f, -(float)i / 64.0f);
    float a = (float)s * freq;
    g_pe[s * D_ + t] = (t & 1) ? cosf(a) : sinf(a);
}

__global__ void kPEmean() {
    int t = threadIdx.x;
    float acc = 0.f;
    #pragma unroll
    for (int s = 0; s < S_; s++) acc += g_pe[s * D_ + t];
    g_pem[t] = acc * (1.0f / (float)S_);
}

__global__ void kT(const float* __restrict__ w_k) {
    int t = threadIdx.x;
    for (int row = 0; row < D_; row++)
        g_wkT[t * D_ + row] = w_k[row * D_ + t];
}

// ---------------------------------------------------------------------------
// Mega kernel: one block per group i. 128 threads.
__global__ void __launch_bounds__(128) kMega(
    const float* __restrict__ x,
    const float* __restrict__ w_q, const float* __restrict__ b_q,
    const float* __restrict__ w2,  const float* __restrict__ b2)
{
    __shared__ float ep[S_ * (D_ + 1)];   // 33024 B, stride-129 (conflict-free both ways)
    __shared__ float rs[4 * H_ * D_];     // 8 KB: r per consumer k, head h: rs[(k*4+h)*128+d]
    __shared__ float pr[4 * H_ * S_];     // 4 KB: probs; also aliased as chain scratch

    // chain scratch aliases pr (dead before probs are written):
    float* em = pr;          // 512 floats: e_mean[k][t]; later reused for q_hat
    float* qm = pr + 512;    // 512 floats: q_mean[k][t]

    const int t = threadIdx.x;
    const int i = blockIdx.x;

    // pe column in registers (used for every tile load)
    float per[S_];
    #pragma unroll
    for (int s = 0; s < S_; s++) per[s] = g_pe[s * D_ + t];
    const float pm = g_pem[t];

    // ---- A1: e_mean for 4 consumers (streaming column sums, no smem tile) ----
    #pragma unroll
    for (int k = 0; k < 4; k++) {
        const float* xb = x + (size_t)(i + 1024 * k) * (S_ * D_) + t;
        float acc = 0.f;
        #pragma unroll
        for (int s = 0; s < S_; s++) acc += xb[s * D_];
        em[k * D_ + t] = acc * (1.0f / (float)S_) + pm;
    }
    __syncthreads();

    // ---- A2: q_mean = e_mean @ w_q + b_q ----
    {
        float acc[4] = {0.f, 0.f, 0.f, 0.f};
        for (int j = 0; j < D_; j++) {
            float wv = w_q[j * D_ + t];
            #pragma unroll
            for (int k = 0; k < 4; k++) acc[k] += em[k * D_ + j] * wv;
        }
        float bq = b_q[t];
        #pragma unroll
        for (int k = 0; k < 4; k++) qm[k * D_ + t] = acc[k] + bq;
    }
    __syncthreads();

    // q_hat = q_mean @ w2 + b2  (overwrites em — em is dead)
    {
        float acc[4] = {0.f, 0.f, 0.f, 0.f};
        for (int j = 0; j < D_; j++) {
            float wv = w2[j * D_ + t];
            #pragma unroll
            for (int k = 0; k < 4; k++) acc[k] += qm[k * D_ + j] * wv;
        }
        float bb = b2[t];
        #pragma unroll
        for (int k = 0; k < 4; k++) em[k * D_ + t] = acc[k] + bb;   // em := q_hat
    }
    __syncthreads();

    // r[k,h,d] = sum_j w_k[d, h*32+j] * q_hat[k, h*32+j]   (b_k cancels in softmax)
    #pragma unroll
    for (int h = 0; h < H_; h++) {
        float acc[4] = {0.f, 0.f, 0.f, 0.f};
        #pragma unroll 8
        for (int j = 0; j < 32; j++) {
            int c = h * 32 + j;
            float wv = g_wkT[c * D_ + t];
            #pragma unroll
            for (int k = 0; k < 4; k++) acc[k] += em[k * D_ + c] * wv;
        }
        #pragma unroll
        for (int k = 0; k < 4; k++) rs[(k * 4 + h) * D_ + t] = acc[k];
    }
    __syncthreads();

    // ---- A3: per consumer: reload tile (L2-hot), scores, softmax -> pr ----
    const float scale = 0.17677669529663689f;  // 1/sqrt(32)
    for (int k = 0; k < 4; k++) {
        const float* xb = x + (size_t)(i + 1024 * k) * (S_ * D_) + t;
        #pragma unroll
        for (int s = 0; s < S_; s++) ep[s * (D_ + 1) + t] = xb[s * D_] + per[s];
        __syncthreads();

        // scores: thread owns s2 = t&63, computes heads hp and hp+2 (shares ep reads)
        {
            int s2 = t & 63;
            int hp = t >> 6;
            float a0 = 0.f, a1 = 0.f;
            const float* r0 = &rs[(k * 4 + hp) * D_];
            const float* r1 = &rs[(k * 4 + hp + 2) * D_];
            #pragma unroll 16
            for (int d = 0; d < D_; d++) {
                float ev = ep[s2 * (D_ + 1) + d];
                a0 += ev * r0[d];
                a1 += ev * r1[d];
            }
            pr[k * 256 + hp * S_ + s2]       = a0 * scale;
            pr[k * 256 + (hp + 2) * S_ + s2] = a1 * scale;
        }
        __syncthreads();

        // softmax in place: warp h handles head h, lane l owns entries l and l+32
        {
            int h = t >> 5, l = t & 31;
            float* pp = &pr[k * 256 + h * S_];
            float v0 = pp[l], v1 = pp[32 + l];
            float mx = fmaxf(v0, v1);
            #pragma unroll
            for (int o = 16; o > 0; o >>= 1) mx = fmaxf(mx, __shfl_xor_sync(0xffffffffu, mx, o));
            float e0 = expf(v0 - mx), e1 = expf(v1 - mx);
            float sum = e0 + e1;
            #pragma unroll
            for (int o = 16; o > 0; o >>= 1) sum += __shfl_xor_sync(0xffffffffu, sum, o);
            float inv = 1.0f / sum;
            pp[l] = e0 * inv;
            pp[32 + l] = e1 * inv;
        }
        __syncthreads();
    }

    // ---- B: source tiles — attn[b=i+1024k, h] += probs[k,h] @ ep(source 4i+h) ----
    #pragma unroll
    for (int h = 0; h < H_; h++) {
        const float* xj = x + (size_t)(4 * i + h) * (S_ * D_) + t;
        #pragma unroll
        for (int s = 0; s < S_; s++) ep[s * (D_ + 1) + t] = xj[s * D_] + per[s];
        __syncthreads();

        float a0 = 0.f, a1 = 0.f, a2 = 0.f, a3 = 0.f;
        #pragma unroll 16
        for (int s = 0; s < S_; s++) {
            float ev = ep[s * (D_ + 1) + t];
            a0 += pr[0 * 256 + h * S_ + s] * ev;
            a1 += pr[1 * 256 + h * S_ + s] * ev;
            a2 += pr[2 * 256 + h * S_ + s] * ev;
            a3 += pr[3 * 256 + h * S_ + s] * ev;
        }
        g_attn[(size_t)(i + 1024 * 0) * 512 + h * D_ + t] = a0;
        g_attn[(size_t)(i + 1024 * 1) * 512 + h * D_ + t] = a1;
        g_attn[(size_t)(i + 1024 * 2) * 512 + h * D_ + t] = a2;
        g_attn[(size_t)(i + 1024 * 3) * 512 + h * D_ + t] = a3;
        __syncthreads();
    }
}

// ---------------------------------------------------------------------------
// MLP: (B,512)@(512,128)+BN+ReLU -> (B,128)@(128,128)+BN+ReLU
__global__ void __launch_bounds__(128) kMLP(
    const float* __restrict__ w3a, const float* __restrict__ b3a,
    const float* __restrict__ g3a, const float* __restrict__ be3a,
    const float* __restrict__ w3b, const float* __restrict__ b3b,
    const float* __restrict__ g3b, const float* __restrict__ be3b,
    float* __restrict__ out)
{
    __shared__ float as[MBE * 512];
    __shared__ float h1[MBE * D_];
    int t = threadIdx.x;
    int b0 = blockIdx.x * MBE;

    const float* ap = g_attn + (size_t)b0 * 512;
    for (int i = t; i < MBE * 512; i += 128) as[i] = ap[i];
    __syncthreads();

    float acc[MBE];
    #pragma unroll
    for (int m = 0; m < MBE; m++) acc[m] = 0.f;
    for (int i = 0; i < 512; i++) {
        float wv = w3a[i * D_ + t];
        #pragma unroll
        for (int m = 0; m < MBE; m++) acc[m] += as[m * 512 + i] * wv;
    }
    {
        float bb = b3a[t], gg = g3a[t], be = be3a[t];
        #pragma unroll
        for (int m = 0; m < MBE; m++) {
            float v = (acc[m] + bb) * gg + be;
            h1[m * D_ + t] = fmaxf(v, 0.f);
        }
    }
    __syncthreads();

    #pragma unroll
    for (int m = 0; m < MBE; m++) acc[m] = 0.f;
    for (int i = 0; i < D_; i++) {
        float wv = w3b[i * D_ + t];
        #pragma unroll
        for (int m = 0; m < MBE; m++) acc[m] += h1[m * D_ + i] * wv;
    }
    {
        float bb = b3b[t], gg = g3b[t], be = be3b[t];
        #pragma unroll
        for (int m = 0; m < MBE; m++) {
            float v = (acc[m] + bb) * gg + be;
            out[(size_t)(b0 + m) * D_ + t] = fmaxf(v, 0.f);
        }
    }
}

// ---------------------------------------------------------------------------
extern "C" void kernel_launch(void* const* d_in, const int* in_sizes, int n_in,
                              void* d_out, int out_size) {
    const float* x    = (const float*)d_in[0];
    const float* w_q  = (const float*)d_in[1];
    const float* b_q  = (const float*)d_in[2];
    const float* w_k  = (const float*)d_in[3];
    // d_in[4] = b_k: constant shift over s -> cancels in softmax. Unused.
    const float* w2   = (const float*)d_in[5];
    const float* b2   = (const float*)d_in[6];
    const float* w3a  = (const float*)d_in[7];
    const float* b3a  = (const float*)d_in[8];
    const float* g3a  = (const float*)d_in[9];
    const float* be3a = (const float*)d_in[10];
    const float* w3b  = (const float*)d_in[11];
    const float* b3b  = (const float*)d_in[12];
    const float* g3b  = (const float*)d_in[13];
    const float* be3b = (const float*)d_in[14];
    float* out = (float*)d_out;

    kPE     <<<S_, D_>>>();
    kPEmean <<<1, D_>>>();
    kT      <<<1, D_>>>(w_k);
    kMega   <<<B_ / 4, D_>>>(x, w_q, b_q, w2, b2);
    kMLP    <<<B_ / MBE, D_>>>(w3a, b3a, g3a, be3a, w3b, b3b, g3b, be3b, out);
}

// round 3
// speedup vs baseline: 1.2419x; 1.1022x over previous
#include <cuda_runtime.h>
#include <math.h>

// TemporalAttentionEncoder — fused group formulation, vectorized.
// Group i in [0,1024): consumers b = i+1024k (k=0..3); attn[b,h] sources x[4i+h].

#define B_   4096
#define S_   64
#define D_   128
#define H_   4
#define EPS  132   // ep row stride in floats (132 mod 32 == 4 -> conflict-free LDS.128)

__device__ __align__(16) float g_pe[S_ * D_];
__device__ __align__(16) float g_pem[D_];
__device__ __align__(16) float g_wkT[D_ * D_];       // wkT[c*128+d] = w_k[d*128+c]
__device__ __align__(16) float g_attn[(size_t)B_ * H_ * D_];  // 8 MB

// ---------------------------------------------------------------------------
__global__ void kPE() {
    int s = blockIdx.x, t = threadIdx.x;
    int i = t >> 1;
    float freq = powf(1000.0f, -(float)i / 64.0f);
    float a = (float)s * freq;
    g_pe[s * D_ + t] = (t & 1) ? cosf(a) : sinf(a);
}

__global__ void kPEmean() {
    int t = threadIdx.x;
    float acc = 0.f;
    #pragma unroll
    for (int s = 0; s < S_; s++) acc += g_pe[s * D_ + t];
    g_pem[t] = acc * (1.0f / (float)S_);
}

// parallel transpose: block = source row d, thread = col c
__global__ void kT(const float* __restrict__ w_k) {
    int d = blockIdx.x, c = threadIdx.x;
    g_wkT[c * D_ + d] = w_k[d * D_ + c];
}

// ---------------------------------------------------------------------------
// Mega kernel: one block per group i, 256 threads.
__global__ void __launch_bounds__(256) kMega(
    const float* __restrict__ x,
    const float* __restrict__ w_q, const float* __restrict__ b_q,
    const float* __restrict__ w2,  const float* __restrict__ b2)
{
    __shared__ __align__(16) float ep[S_ * EPS];   // 33792 B tile (also A1 scratch)
    __shared__ __align__(16) float rs[16 * D_];    // 8 KB  r[(k*4+h)*128+d]
    __shared__ __align__(16) float pr[1024];       // 4 KB  probs[k*256+h*64+s]; aliases em/qm

    float* em = pr;         // 512 floats (e_mean, later q_hat)
    float* qm = pr + 512;   // 512 floats (q_mean)

    const int t = threadIdx.x;
    const int i = blockIdx.x;
    const int c  = t & 31;   // float4 column
    const int r0 = t >> 5;   // row phase 0..7
    const int d  = t & 127;
    const int g  = t >> 7;   // 0/1

    // ---- A1: e_mean partials for 4 consumers (float4 streaming) ----
    float4* eps4 = (float4*)ep;
    #pragma unroll
    for (int k = 0; k < 4; k++) {
        const float4* xb = (const float4*)(x + (size_t)(i + 1024 * k) * (S_ * D_));
        float4 v[8];
        #pragma unroll
        for (int j = 0; j < 8; j++) v[j] = xb[(r0 + 8 * j) * 32 + c];
        float4 a = v[0];
        #pragma unroll
        for (int j = 1; j < 8; j++) { a.x += v[j].x; a.y += v[j].y; a.z += v[j].z; a.w += v[j].w; }
        eps4[k * 256 + r0 * 32 + c] = a;
    }
    __syncthreads();
    if (t < 128) {
        const int kk = t >> 5, cc = t & 31;
        float4 a = eps4[kk * 256 + cc];
        #pragma unroll
        for (int r = 1; r < 8; r++) {
            float4 v = eps4[kk * 256 + r * 32 + cc];
            a.x += v.x; a.y += v.y; a.z += v.z; a.w += v.w;
        }
        float4 pm = *((const float4*)g_pem + cc);
        const float inv = 1.0f / (float)S_;
        a.x = a.x * inv + pm.x; a.y = a.y * inv + pm.y;
        a.z = a.z * inv + pm.z; a.w = a.w * inv + pm.w;
        // NOTE: must not write into pr (aliases eps4 source) before all reads done
        __syncwarp();
        ((float4*)em)[kk * 32 + cc] = a;
    }
    __syncthreads();

    // ---- A2: q_mean = em @ w_q + b_q  (thread: output d for k=g and k=g+2) ----
    {
        float a0 = 0.f, a1 = 0.f;
        #pragma unroll 4
        for (int j = 0; j < D_; j++) {
            float wv = w_q[j * D_ + d];
            a0 += em[g * D_ + j] * wv;
            a1 += em[(g + 2) * D_ + j] * wv;
        }
        float bq = b_q[d];
        qm[g * D_ + d] = a0 + bq;
        qm[(g + 2) * D_ + d] = a1 + bq;
    }
    __syncthreads();
    // q_hat = qm @ w2 + b2 -> overwrite em
    {
        float a0 = 0.f, a1 = 0.f;
        #pragma unroll 4
        for (int j = 0; j < D_; j++) {
            float wv = w2[j * D_ + d];
            a0 += qm[g * D_ + j] * wv;
            a1 += qm[(g + 2) * D_ + j] * wv;
        }
        float bb = b2[d];
        em[g * D_ + d] = a0 + bb;
        em[(g + 2) * D_ + d] = a1 + bb;
    }
    __syncthreads();
    // r[k,h,d] = sum_{j<32} wkT[h*32+j][d] * q_hat[k][h*32+j]  (b_k cancels)
    #pragma unroll
    for (int h = 0; h < H_; h++) {
        float a0 = 0.f, a1 = 0.f;
        #pragma unroll 8
        for (int j = 0; j < 32; j++) {
            float wv = g_wkT[(h * 32 + j) * D_ + d];
            a0 += em[g * D_ + h * 32 + j] * wv;
            a1 += em[(g + 2) * D_ + h * 32 + j] * wv;
        }
        rs[(g * 4 + h) * D_ + d] = a0;
        rs[((g + 2) * 4 + h) * D_ + d] = a1;
    }
    __syncthreads();

    // ---- A3: per consumer k: stage tile (L2-hot), scores, softmax -> pr ----
    const float scale = 0.17677669529663689f;  // 1/sqrt(32)
    for (int k = 0; k < 4; k++) {
        const float4* xb = (const float4*)(x + (size_t)(i + 1024 * k) * (S_ * D_));
        const float4* pe4 = (const float4*)g_pe;
        #pragma unroll
        for (int j = 0; j < 8; j++) {
            int row = r0 + 8 * j;
            float4 v = xb[row * 32 + c];
            float4 p = __ldg(pe4 + row * 32 + c);
            v.x += p.x; v.y += p.y; v.z += p.z; v.w += p.w;
            *(float4*)&ep[row * EPS + 4 * c] = v;
        }
        __syncthreads();
        // scores: thread (h = t>>6, s = t&63), vectorized row dot
        {
            const int h = t >> 6, s = t & 63;
            const float4* er = (const float4*)&ep[s * EPS];
            const float4* rr = (const float4*)&rs[(k * 4 + h) * D_];
            float a = 0.f;
            #pragma unroll 8
            for (int j = 0; j < 32; j++) {
                float4 e = er[j];
                float4 w = rr[j];  // warp-uniform broadcast
                a += e.x * w.x + e.y * w.y + e.z * w.z + e.w * w.w;
            }
            pr[k * 256 + h * 64 + s] = a * scale;
        }
        __syncthreads();
        // softmax in place (first 128 threads)
        if (t < 128) {
            int h = t >> 5, l = t & 31;
            float* pp = &pr[k * 256 + h * 64];
            float v0 = pp[l], v1 = pp[32 + l];
            float mx = fmaxf(v0, v1);
            #pragma unroll
            for (int o = 16; o > 0; o >>= 1) mx = fmaxf(mx, __shfl_xor_sync(0xffffffffu, mx, o));
            float e0 = expf(v0 - mx), e1 = expf(v1 - mx);
            float sum = e0 + e1;
            #pragma unroll
            for (int o = 16; o > 0; o >>= 1) sum += __shfl_xor_sync(0xffffffffu, sum, o);
            float inv = 1.0f / sum;
            pp[l] = e0 * inv;
            pp[32 + l] = e1 * inv;
        }
        __syncthreads();
    }

    // ---- B: source tiles h: attn[b=i+1024k, h] = probs[k,h] @ ep(source 4i+h) ----
    for (int h = 0; h < H_; h++) {
        const float4* xj = (const float4*)(x + (size_t)(4 * i + h) * (S_ * D_));
        const float4* pe4 = (const float4*)g_pe;
        #pragma unroll
        for (int j = 0; j < 8; j++) {
            int row = r0 + 8 * j;
            float4 v = xj[row * 32 + c];
            float4 p = __ldg(pe4 + row * 32 + c);
            v.x += p.x; v.y += p.y; v.z += p.z; v.w += p.w;
            *(float4*)&ep[row * EPS + 4 * c] = v;
        }
        __syncthreads();
        {
            float a0 = 0.f, a1 = 0.f;
            const float* p0 = &pr[g * 256 + h * 64];
            const float* p1 = &pr[(g + 2) * 256 + h * 64];
            #pragma unroll 16
            for (int s = 0; s < S_; s++) {
                float ev = ep[s * EPS + d];
                a0 += p0[s] * ev;
                a1 += p1[s] * ev;
            }
            g_attn[(size_t)(i + 1024 * g) * 512 + h * D_ + d] = a0;
            g_attn[(size_t)(i + 1024 * (g + 2)) * 512 + h * D_ + d] = a1;
        }
        __syncthreads();
    }
}

// ---------------------------------------------------------------------------
// MLP: register-blocked, float4 operand reads. 16 batches/block, 256 threads.
__global__ void __launch_bounds__(256) kMLP(
    const float* __restrict__ w3a, const float* __restrict__ b3a,
    const float* __restrict__ g3a, const float* __restrict__ be3a,
    const float* __restrict__ w3b, const float* __restrict__ b3b,
    const float* __restrict__ g3b, const float* __restrict__ be3b,
    float* __restrict__ out)
{
    __shared__ __align__(16) float as[16 * 512];  // 32 KB
    __shared__ __align__(16) float h1[16 * D_];   // 8 KB
    const int t = threadIdx.x;
    const int b0 = blockIdx.x * 16;
    const int d = t & 127, g = t >> 7;  // g: batch-half (8 batches each)

    const float4* ap = (const float4*)(g_attn + (size_t)b0 * 512);
    float4* as4 = (float4*)as;
    #pragma unroll
    for (int j = 0; j < 8; j++) as4[t + 256 * j] = ap[t + 256 * j];
    __syncthreads();

    float acc[8];
    #pragma unroll
    for (int m = 0; m < 8; m++) acc[m] = 0.f;
    for (int i0 = 0; i0 < 512; i0 += 4) {
        float wv0 = w3a[(i0 + 0) * D_ + d];
        float wv1 = w3a[(i0 + 1) * D_ + d];
        float wv2 = w3a[(i0 + 2) * D_ + d];
        float wv3 = w3a[(i0 + 3) * D_ + d];
        #pragma unroll
        for (int m = 0; m < 8; m++) {
            float4 av = *(const float4*)&as[(g * 8 + m) * 512 + i0];  // broadcast
            acc[m] += av.x * wv0 + av.y * wv1 + av.z * wv2 + av.w * wv3;
        }
    }
    {
        float bb = b3a[d], gg = g3a[d], be = be3a[d];
        #pragma unroll
        for (int m = 0; m < 8; m++) {
            float v = (acc[m] + bb) * gg + be;
            h1[(g * 8 + m) * D_ + d] = fmaxf(v, 0.f);
        }
    }
    __syncthreads();

    #pragma unroll
    for (int m = 0; m < 8; m++) acc[m] = 0.f;
    for (int i0 = 0; i0 < D_; i0 += 4) {
        float wv0 = w3b[(i0 + 0) * D_ + d];
        float wv1 = w3b[(i0 + 1) * D_ + d];
        float wv2 = w3b[(i0 + 2) * D_ + d];
        float wv3 = w3b[(i0 + 3) * D_ + d];
        #pragma unroll
        for (int m = 0; m < 8; m++) {
            float4 hv = *(const float4*)&h1[(g * 8 + m) * D_ + i0];
            acc[m] += hv.x * wv0 + hv.y * wv1 + hv.z * wv2 + hv.w * wv3;
        }
    }
    {
        float bb = b3b[d], gg = g3b[d], be = be3b[d];
        #pragma unroll
        for (int m = 0; m < 8; m++) {
            float v = (acc[m] + bb) * gg + be;
            out[(size_t)(b0 + g * 8 + m) * D_ + d] = fmaxf(v, 0.f);
        }
    }
}

// ---------------------------------------------------------------------------
extern "C" void kernel_launch(void* const* d_in, const int* in_sizes, int n_in,
                              void* d_out, int out_size) {
    const float* x    = (const float*)d_in[0];
    const float* w_q  = (const float*)d_in[1];
    const float* b_q  = (const float*)d_in[2];
    const float* w_k  = (const float*)d_in[3];
    // d_in[4] = b_k: constant shift over s -> cancels in softmax. Unused.
    const float* w2   = (const float*)d_in[5];
    const float* b2   = (const float*)d_in[6];
    const float* w3a  = (const float*)d_in[7];
    const float* b3a  = (const float*)d_in[8];
    const float* g3a  = (const float*)d_in[9];
    const float* be3a = (const float*)d_in[10];
    const float* w3b  = (const float*)d_in[11];
    const float* b3b  = (const float*)d_in[12];
    const float* g3b  = (const float*)d_in[13];
    const float* be3b = (const float*)d_in[14];
    float* out = (float*)d_out;

    kPE     <<<S_, D_>>>();
    kPEmean <<<1, D_>>>();
    kT      <<<D_, D_>>>(w_k);
    kMega   <<<B_ / 4, 256>>>(x, w_q, b_q, w2, b2);
    kMLP    <<<B_ / 16, 256>>>(w3a, b3a, g3a, be3a, w3b, b3b, g3b, be3b, out);
}

// round 4
// speedup vs baseline: 1.4170x; 1.1410x over previous
#include <cuda_runtime.h>
#include <math.h>

// TemporalAttentionEncoder — 3 streaming passes + tiny GEMM kernels.
//   pass1 kMean  : e_mean[b] = mean_S(x[b]) + pe_mean
//   kChain       : q_mean -> q_hat -> r   (b_k cancels in softmax)
//   pass2 kScores: probs[b,h,s] = softmax_s( (x[b,s]+pe[s]) . r[b,h] / sqrt(32) )
//   pass3 kAttn  : attn[b,h] = probs[b,h] @ (x[(4b+h)%B] + pe)   (torch tile quirk)
//   kMLP         : two Linear+BN+ReLU layers

#define B_   4096
#define S_   64
#define D_   128
#define H_   4
#define EPS  132   // ep row stride in floats (conflict-free for row float4 and col reads)

__device__ __align__(16) float g_pe[S_ * D_];
__device__ __align__(16) float g_pem[D_];
__device__ __align__(16) float g_wkT[D_ * D_];                 // wkT[c*128+d] = w_k[d*128+c]
__device__ __align__(16) float g_emean[(size_t)B_ * D_];       // 2 MB
__device__ __align__(16) float g_r[(size_t)B_ * H_ * D_];      // 8 MB
__device__ __align__(16) float g_probs[(size_t)B_ * H_ * S_];  // 4 MB
__device__ __align__(16) float g_attn[(size_t)B_ * H_ * D_];   // 8 MB

// ---------------------------------------------------------------------------
__global__ void kPE() {
    int s = blockIdx.x, t = threadIdx.x;
    int i = t >> 1;
    float freq = powf(1000.0f, -(float)i / 64.0f);
    float a = (float)s * freq;
    g_pe[s * D_ + t] = (t & 1) ? cosf(a) : sinf(a);
}

__global__ void kPEmean() {
    int t = threadIdx.x;
    float acc = 0.f;
    #pragma unroll
    for (int s = 0; s < S_; s++) acc += g_pe[s * D_ + t];
    g_pem[t] = acc * (1.0f / (float)S_);
}

__global__ void kT(const float* __restrict__ w_k) {
    int d = blockIdx.x, c = threadIdx.x;
    g_wkT[c * D_ + d] = w_k[d * D_ + c];
}

// ---------------------------------------------------------------------------
// Pass 1: e_mean. One block per batch; 256 threads; 8 independent LDG.128 each.
__global__ void __launch_bounds__(256) kMean(const float* __restrict__ x) {
    __shared__ __align__(16) float4 red[256];
    const int t = threadIdx.x, b = blockIdx.x;
    const int c = t & 31, r0 = t >> 5;
    const float4* xb = (const float4*)(x + (size_t)b * (S_ * D_));

    float4 v[8];
    #pragma unroll
    for (int j = 0; j < 8; j++) v[j] = xb[(r0 + 8 * j) * 32 + c];
    float4 a = v[0];
    #pragma unroll
    for (int j = 1; j < 8; j++) { a.x += v[j].x; a.y += v[j].y; a.z += v[j].z; a.w += v[j].w; }
    red[r0 * 32 + c] = a;
    __syncthreads();

    if (t < 32) {
        float4 s = red[t];
        #pragma unroll
        for (int r = 1; r < 8; r++) {
            float4 u = red[r * 32 + t];
            s.x += u.x; s.y += u.y; s.z += u.z; s.w += u.w;
        }
        const float inv = 1.0f / (float)S_;
        float4 pm = ((const float4*)g_pem)[t];
        s.x = s.x * inv + pm.x; s.y = s.y * inv + pm.y;
        s.z = s.z * inv + pm.z; s.w = s.w * inv + pm.w;
        ((float4*)g_emean)[(size_t)b * 32 + t] = s;
    }
}

// ---------------------------------------------------------------------------
// Chain: q_mean = em@w_q+b_q ; q_hat = qm@w2+b2 ; r[b,h,d].
// 8 batches/block, 256 threads: thread = (d = t&127, g = t>>7); g half owns 4 batches.
__global__ void __launch_bounds__(256) kChain(
    const float* __restrict__ w_q, const float* __restrict__ b_q,
    const float* __restrict__ w2,  const float* __restrict__ b2)
{
    __shared__ float em[8 * D_];
    __shared__ float qm[8 * D_];
    __shared__ float qh[8 * D_];
    const int t = threadIdx.x;
    const int b0 = blockIdx.x * 8;
    const int d = t & 127, g = t >> 7;

    #pragma unroll
    for (int j = 0; j < 4; j++) em[t + 256 * j] = g_emean[(size_t)b0 * D_ + t + 256 * j];
    __syncthreads();

    {
        float acc[4] = {0.f, 0.f, 0.f, 0.f};
        for (int j = 0; j < D_; j++) {
            float wv = w_q[j * D_ + d];
            #pragma unroll
            for (int m = 0; m < 4; m++) acc[m] += em[(g * 4 + m) * D_ + j] * wv;
        }
        float bq = b_q[d];
        #pragma unroll
        for (int m = 0; m < 4; m++) qm[(g * 4 + m) * D_ + d] = acc[m] + bq;
    }
    __syncthreads();
    {
        float acc[4] = {0.f, 0.f, 0.f, 0.f};
        for (int j = 0; j < D_; j++) {
            float wv = w2[j * D_ + d];
            #pragma unroll
            for (int m = 0; m < 4; m++) acc[m] += qm[(g * 4 + m) * D_ + j] * wv;
        }
        float bb = b2[d];
        #pragma unroll
        for (int m = 0; m < 4; m++) qh[(g * 4 + m) * D_ + d] = acc[m] + bb;
    }
    __syncthreads();
    #pragma unroll
    for (int h = 0; h < H_; h++) {
        float acc[4] = {0.f, 0.f, 0.f, 0.f};
        #pragma unroll 8
        for (int j = 0; j < 32; j++) {
            float wv = g_wkT[(h * 32 + j) * D_ + d];
            #pragma unroll
            for (int m = 0; m < 4; m++) acc[m] += qh[(g * 4 + m) * D_ + h * 32 + j] * wv;
        }
        #pragma unroll
        for (int m = 0; m < 4; m++)
            g_r[((size_t)(b0 + g * 4 + m) * H_ + h) * D_ + d] = acc[m];
    }
}

// ---------------------------------------------------------------------------
// Pass 2: scores + softmax. One block per batch; 256 threads.
__global__ void __launch_bounds__(256) kScores(const float* __restrict__ x) {
    __shared__ __align__(16) float ep[S_ * EPS];   // ~33 KB
    __shared__ __align__(16) float rs[H_ * D_];    // 2 KB
    __shared__ float sc[H_ * S_];                  // 1 KB
    const int t = threadIdx.x, b = blockIdx.x;
    const int c = t & 31, r0 = t >> 5;

    const float4* xb  = (const float4*)(x + (size_t)b * (S_ * D_));
    const float4* pe4 = (const float4*)g_pe;
    #pragma unroll
    for (int j = 0; j < 8; j++) {
        int row = r0 + 8 * j;
        float4 v = xb[row * 32 + c];
        float4 p = __ldg(pe4 + row * 32 + c);
        v.x += p.x; v.y += p.y; v.z += p.z; v.w += p.w;
        *(float4*)&ep[row * EPS + 4 * c] = v;
    }
    if (t < 128) ((float4*)rs)[t] = ((const float4*)(g_r + (size_t)b * (H_ * D_)))[t];
    __syncthreads();

    // scores: thread = (h = t>>6, s = t&63); row dot via LDS.128
    {
        const int h = t >> 6, s = t & 63;
        const float4* er = (const float4*)&ep[s * EPS];
        const float4* rr = (const float4*)&rs[h * D_];
        float a = 0.f;
        #pragma unroll 8
        for (int j = 0; j < 32; j++) {
            float4 e = er[j];
            float4 w = rr[j];   // warp-uniform broadcast
            a += e.x * w.x + e.y * w.y + e.z * w.z + e.w * w.w;
        }
        sc[h * S_ + s] = a * 0.17677669529663689f;  // 1/sqrt(32)
    }
    __syncthreads();

    if (t < 128) {
        int h = t >> 5, l = t & 31;
        const float* pp = &sc[h * S_];
        float v0 = pp[l], v1 = pp[32 + l];
        float mx = fmaxf(v0, v1);
        #pragma unroll
        for (int o = 16; o > 0; o >>= 1) mx = fmaxf(mx, __shfl_xor_sync(0xffffffffu, mx, o));
        float e0 = expf(v0 - mx), e1 = expf(v1 - mx);
        float sum = e0 + e1;
        #pragma unroll
        for (int o = 16; o > 0; o >>= 1) sum += __shfl_xor_sync(0xffffffffu, sum, o);
        float inv = 1.0f / sum;
        float* po = g_probs + ((size_t)b * H_ + h) * S_;
        po[l] = e0 * inv;
        po[32 + l] = e1 * inv;
    }
}

// ---------------------------------------------------------------------------
// Pass 3: attention. One block per SOURCE batch j; consumers b=(j>>2)+1024k, h=j&3.
__global__ void __launch_bounds__(256) kAttn(const float* __restrict__ x) {
    __shared__ __align__(16) float ep[S_ * EPS];
    __shared__ float pr[4 * S_];
    const int t = threadIdx.x, j = blockIdx.x;
    const int c = t & 31, r0 = t >> 5;
    const int h = j & 3, bb = j >> 2;

    const float4* xj  = (const float4*)(x + (size_t)j * (S_ * D_));
    const float4* pe4 = (const float4*)g_pe;
    #pragma unroll
    for (int q = 0; q < 8; q++) {
        int row = r0 + 8 * q;
        float4 v = xj[row * 32 + c];
        float4 p = __ldg(pe4 + row * 32 + c);
        v.x += p.x; v.y += p.y; v.z += p.z; v.w += p.w;
        *(float4*)&ep[row * EPS + 4 * c] = v;
    }
    if (t < S_) {
        #pragma unroll
        for (int k = 0; k < 4; k++)
            pr[k * S_ + t] = g_probs[((size_t)(bb + 1024 * k) * H_ + h) * S_ + t];
    }
    __syncthreads();

    const int d = t & 127, gk = t >> 7;   // thread handles consumers k=gk and gk+2
    float a0 = 0.f, a1 = 0.f;
    const float* p0 = &pr[gk * S_];
    const float* p1 = &pr[(gk + 2) * S_];
    #pragma unroll 16
    for (int s = 0; s < S_; s++) {
        float ev = ep[s * EPS + d];
        a0 += p0[s] * ev;
        a1 += p1[s] * ev;
    }
    g_attn[(size_t)(bb + 1024 * gk) * 512 + h * D_ + d] = a0;
    g_attn[(size_t)(bb + 1024 * (gk + 2)) * 512 + h * D_ + d] = a1;
}

// ---------------------------------------------------------------------------
// MLP: register-blocked, float4 operand reads. 16 batches/block, 256 threads.
__global__ void __launch_bounds__(256) kMLP(
    const float* __restrict__ w3a, const float* __restrict__ b3a,
    const float* __restrict__ g3a, const float* __restrict__ be3a,
    const float* __restrict__ w3b, const float* __restrict__ b3b,
    const float* __restrict__ g3b, const float* __restrict__ be3b,
    float* __restrict__ out)
{
    __shared__ __align__(16) float as[16 * 512];
    __shared__ __align__(16) float h1[16 * D_];
    const int t = threadIdx.x;
    const int b0 = blockIdx.x * 16;
    const int d = t & 127, g = t >> 7;

    const float4* ap = (const float4*)(g_attn + (size_t)b0 * 512);
    float4* as4 = (float4*)as;
    #pragma unroll
    for (int j = 0; j < 8; j++) as4[t + 256 * j] = ap[t + 256 * j];
    __syncthreads();

    float acc[8];
    #pragma unroll
    for (int m = 0; m < 8; m++) acc[m] = 0.f;
    for (int i0 = 0; i0 < 512; i0 += 4) {
        float wv0 = w3a[(i0 + 0) * D_ + d];
        float wv1 = w3a[(i0 + 1) * D_ + d];
        float wv2 = w3a[(i0 + 2) * D_ + d];
        float wv3 = w3a[(i0 + 3) * D_ + d];
        #pragma unroll
        for (int m = 0; m < 8; m++) {
            float4 av = *(const float4*)&as[(g * 8 + m) * 512 + i0];
            acc[m] += av.x * wv0 + av.y * wv1 + av.z * wv2 + av.w * wv3;
        }
    }
    {
        float bb = b3a[d], gg = g3a[d], be = be3a[d];
        #pragma unroll
        for (int m = 0; m < 8; m++) {
            float v = (acc[m] + bb) * gg + be;
            h1[(g * 8 + m) * D_ + d] = fmaxf(v, 0.f);
        }
    }
    __syncthreads();

    #pragma unroll
    for (int m = 0; m < 8; m++) acc[m] = 0.f;
    for (int i0 = 0; i0 < D_; i0 += 4) {
        float wv0 = w3b[(i0 + 0) * D_ + d];
        float wv1 = w3b[(i0 + 1) * D_ + d];
        float wv2 = w3b[(i0 + 2) * D_ + d];
        float wv3 = w3b[(i0 + 3) * D_ + d];
        #pragma unroll
        for (int m = 0; m < 8; m++) {
            float4 hv = *(const float4*)&h1[(g * 8 + m) * D_ + i0];
            acc[m] += hv.x * wv0 + hv.y * wv1 + hv.z * wv2 + hv.w * wv3;
        }
    }
    {
        float bb = b3b[d], gg = g3b[d], be = be3b[d];
        #pragma unroll
        for (int m = 0; m < 8; m++) {
            float v = (acc[m] + bb) * gg + be;
            out[(size_t)(b0 + g * 8 + m) * D_ + d] = fmaxf(v, 0.f);
        }
    }
}

// ---------------------------------------------------------------------------
extern "C" void kernel_launch(void* const* d_in, const int* in_sizes, int n_in,
                              void* d_out, int out_size) {
    const float* x    = (const float*)d_in[0];
    const float* w_q  = (const float*)d_in[1];
    const float* b_q  = (const float*)d_in[2];
    const float* w_k  = (const float*)d_in[3];
    // d_in[4] = b_k: constant over s -> cancels in softmax. Unused.
    const float* w2   = (const float*)d_in[5];
    const float* b2   = (const float*)d_in[6];
    const float* w3a  = (const float*)d_in[7];
    const float* b3a  = (const float*)d_in[8];
    const float* g3a  = (const float*)d_in[9];
    const float* be3a = (const float*)d_in[10];
    const float* w3b  = (const float*)d_in[11];
    const float* b3b  = (const float*)d_in[12];
    const float* g3b  = (const float*)d_in[13];
    const float* be3b = (const float*)d_in[14];
    float* out = (float*)d_out;

    kPE     <<<S_, D_>>>();
    kPEmean <<<1, D_>>>();
    kT      <<<D_, D_>>>(w_k);
    kMean   <<<B_, 256>>>(x);
    kChain  <<<B_ / 8, 256>>>(w_q, b_q, w2, b2);
    kScores <<<B_, 256>>>(x);
    kAttn   <<<B_, 256>>>(x);
    kMLP    <<<B_ / 16, 256>>>(w3a, b3a, g3a, be3a, w3b, b3b, g3b, be3b, out);
}

// round 5
// speedup vs baseline: 1.6061x; 1.1335x over previous
#include <cuda_runtime.h>
#include <cuda_fp16.h>
#include <math.h>

// TemporalAttentionEncoder — fp16 e_p staging, L2-resident passes 2/3.
//   kSetup  : pe table + w_k transpose
//   kMeanEP : e_p = x+pe -> fp16 (64MB, L2-resident); e_mean (fp32 exact)
//   kChain  : q_mean -> q_hat -> r  (b_k cancels in softmax)
//   kScores : probs = softmax( e_p16 . r / sqrt(32) )
//   kAttn   : attn[b,h] = probs[b,h] @ e_p16[(4b+h) mod B]   (torch tile quirk)
//   kMLP    : two Linear+BN+ReLU layers

#define B_   4096
#define S_   64
#define D_   128
#define H_   4
#define EPS  132   // fp32 smem row stride (conflict-free LDS.128 / STS.128 phases)

__device__ __align__(16) float  g_pe[S_ * D_];
__device__ __align__(16) float  g_wkT[D_ * D_];                 // wkT[c*128+d] = w_k[d*128+c]
__device__ __align__(16) __half g_ep16[(size_t)B_ * S_ * D_];   // 64 MB
__device__ __align__(16) float  g_emean[(size_t)B_ * D_];       // 2 MB
__device__ __align__(16) float  g_r[(size_t)B_ * H_ * D_];      // 8 MB
__device__ __align__(16) float  g_probs[(size_t)B_ * H_ * S_];  // 4 MB
__device__ __align__(16) float  g_attn[(size_t)B_ * H_ * D_];   // 8 MB

// ---------------------------------------------------------------------------
// Setup: blocks 0..63 build pe rows; blocks 64..191 transpose w_k row (b-64).
__global__ void kSetup(const float* __restrict__ w_k) {
    int b = blockIdx.x, t = threadIdx.x;
    if (b < 64) {
        int i = t >> 1;
        float freq = powf(1000.0f, -(float)i / 64.0f);
        float a = (float)b * freq;
        g_pe[b * D_ + t] = (t & 1) ? cosf(a) : sinf(a);
    } else {
        int d = b - 64;
        g_wkT[t * D_ + d] = w_k[d * D_ + t];
    }
}

// ---------------------------------------------------------------------------
// Pass 1: e_p -> fp16 global; e_mean (fp32). One block per batch, 256 threads.
__global__ void __launch_bounds__(256) kMeanEP(const float* __restrict__ x) {
    __shared__ __align__(16) float4 red[256];
    const int t = threadIdx.x, b = blockIdx.x;
    const int c = t & 31, r0 = t >> 5;
    const float4* xb  = (const float4*)(x + (size_t)b * (S_ * D_));
    const float4* pe4 = (const float4*)g_pe;

    float4 acc = make_float4(0.f, 0.f, 0.f, 0.f);
    #pragma unroll
    for (int j = 0; j < 8; j++) {
        int row = r0 + 8 * j;
        float4 v = xb[row * 32 + c];
        float4 p = __ldg(pe4 + row * 32 + c);
        v.x += p.x; v.y += p.y; v.z += p.z; v.w += p.w;
        acc.x += v.x; acc.y += v.y; acc.z += v.z; acc.w += v.w;
        __half2 h0 = __floats2half2_rn(v.x, v.y);
        __half2 h1 = __floats2half2_rn(v.z, v.w);
        uint2 u;
        u.x = *(unsigned int*)&h0;
        u.y = *(unsigned int*)&h1;
        *(uint2*)&g_ep16[((size_t)b * S_ + row) * D_ + 4 * c] = u;
    }
    red[r0 * 32 + c] = acc;
    __syncthreads();

    if (t < 32) {
        float4 s = red[t];
        #pragma unroll
        for (int r = 1; r < 8; r++) {
            float4 u = red[r * 32 + t];
            s.x += u.x; s.y += u.y; s.z += u.z; s.w += u.w;
        }
        const float inv = 1.0f / (float)S_;
        s.x *= inv; s.y *= inv; s.z *= inv; s.w *= inv;
        ((float4*)g_emean)[(size_t)b * 32 + t] = s;
    }
}

// ---------------------------------------------------------------------------
// Chain: q_mean = em@w_q+b_q ; q_hat = qm@w2+b2 ; r.  8 batches/block.
__global__ void __launch_bounds__(256) kChain(
    const float* __restrict__ w_q, const float* __restrict__ b_q,
    const float* __restrict__ w2,  const float* __restrict__ b2)
{
    __shared__ float em[8 * D_];
    __shared__ float qm[8 * D_];
    __shared__ float qh[8 * D_];
    const int t = threadIdx.x;
    const int b0 = blockIdx.x * 8;
    const int d = t & 127, g = t >> 7;

    #pragma unroll
    for (int j = 0; j < 4; j++) em[t + 256 * j] = g_emean[(size_t)b0 * D_ + t + 256 * j];
    __syncthreads();

    {
        float acc[4] = {0.f, 0.f, 0.f, 0.f};
        for (int j = 0; j < D_; j++) {
            float wv = w_q[j * D_ + d];
            #pragma unroll
            for (int m = 0; m < 4; m++) acc[m] += em[(g * 4 + m) * D_ + j] * wv;
        }
        float bq = b_q[d];
        #pragma unroll
        for (int m = 0; m < 4; m++) qm[(g * 4 + m) * D_ + d] = acc[m] + bq;
    }
    __syncthreads();
    {
        float acc[4] = {0.f, 0.f, 0.f, 0.f};
        for (int j = 0; j < D_; j++) {
            float wv = w2[j * D_ + d];
            #pragma unroll
            for (int m = 0; m < 4; m++) acc[m] += qm[(g * 4 + m) * D_ + j] * wv;
        }
        float bb = b2[d];
        #pragma unroll
        for (int m = 0; m < 4; m++) qh[(g * 4 + m) * D_ + d] = acc[m] + bb;
    }
    __syncthreads();
    #pragma unroll
    for (int h = 0; h < H_; h++) {
        float acc[4] = {0.f, 0.f, 0.f, 0.f};
        #pragma unroll 8
        for (int j = 0; j < 32; j++) {
            float wv = g_wkT[(h * 32 + j) * D_ + d];
            #pragma unroll
            for (int m = 0; m < 4; m++) acc[m] += qh[(g * 4 + m) * D_ + h * 32 + j] * wv;
        }
        #pragma unroll
        for (int m = 0; m < 4; m++)
            g_r[((size_t)(b0 + g * 4 + m) * H_ + h) * D_ + d] = acc[m];
    }
}

// ---------------------------------------------------------------------------
// Pass 2: scores + softmax from e_p16. One block per batch; 128 threads.
// Thread (g = t>>6, s = t&63) computes heads g and g+2, sharing each ep row read.
__global__ void __launch_bounds__(128) kScores(int dummy) {
    __shared__ __align__(16) float ep[S_ * EPS];   // ~33 KB fp32 tile
    __shared__ __align__(16) float rs[H_ * D_];    // 2 KB
    __shared__ float sc[H_ * S_];                  // 1 KB
    const int t = threadIdx.x, b = blockIdx.x;

    // Stage: 2048 uint2 chunks (4 halves) -> fp32 smem, conflict-free STS.128
    const __half* epg = g_ep16 + (size_t)b * (S_ * D_);
    #pragma unroll
    for (int j = 0; j < 16; j++) {
        int q = t + 128 * j;
        int row = q >> 5, c = q & 31;
        uint2 u = *(const uint2*)&epg[row * D_ + 4 * c];
        __half2 h0 = *(__half2*)&u.x;
        __half2 h1 = *(__half2*)&u.y;
        float2 f0 = __half22float2(h0);
        float2 f1 = __half22float2(h1);
        *(float4*)&ep[row * EPS + 4 * c] = make_float4(f0.x, f0.y, f1.x, f1.y);
    }
    ((float4*)rs)[t] = ((const float4*)(g_r + (size_t)b * (H_ * D_)))[t];
    __syncthreads();

    // scores: 2 heads per thread
    {
        const int g = t >> 6, s = t & 63;
        const float4* er = (const float4*)&ep[s * EPS];
        const float4* r0 = (const float4*)&rs[g * D_];
        const float4* r1 = (const float4*)&rs[(g + 2) * D_];
        float a0 = 0.f, a1 = 0.f;
        #pragma unroll 8
        for (int j = 0; j < 32; j++) {
            float4 e  = er[j];
            float4 w0 = r0[j];   // warp-uniform broadcast
            float4 w1 = r1[j];
            a0 += e.x * w0.x + e.y * w0.y + e.z * w0.z + e.w * w0.w;
            a1 += e.x * w1.x + e.y * w1.y + e.z * w1.z + e.w * w1.w;
        }
        const float scale = 0.17677669529663689f;  // 1/sqrt(32)
        sc[g * S_ + s]       = a0 * scale;
        sc[(g + 2) * S_ + s] = a1 * scale;
    }
    __syncthreads();

    // softmax: warp h handles head h; lane l owns entries l, l+32
    {
        int h = t >> 5, l = t & 31;
        const float* pp = &sc[h * S_];
        float v0 = pp[l], v1 = pp[32 + l];
        float mx = fmaxf(v0, v1);
        #pragma unroll
        for (int o = 16; o > 0; o >>= 1) mx = fmaxf(mx, __shfl_xor_sync(0xffffffffu, mx, o));
        float e0 = expf(v0 - mx), e1 = expf(v1 - mx);
        float sum = e0 + e1;
        #pragma unroll
        for (int o = 16; o > 0; o >>= 1) sum += __shfl_xor_sync(0xffffffffu, sum, o);
        float inv = 1.0f / sum;
        float* po = g_probs + ((size_t)b * H_ + h) * S_;
        po[l] = e0 * inv;
        po[32 + l] = e1 * inv;
    }
}

// ---------------------------------------------------------------------------
// Pass 3: attention from e_p16. One block per SOURCE batch j; 256 threads.
// Consumers b = (j>>2)+1024k on head h = j&3.
__global__ void __launch_bounds__(256) kAttn(int dummy) {
    __shared__ __align__(16) float ep[S_ * EPS];
    __shared__ float pr[4 * S_];
    const int t = threadIdx.x, j = blockIdx.x;
    const int h = j & 3, bb = j >> 2;

    const __half* epg = g_ep16 + (size_t)j * (S_ * D_);
    #pragma unroll
    for (int q0 = 0; q0 < 8; q0++) {
        int q = t + 256 * q0;
        int row = q >> 5, c = q & 31;
        uint2 u = *(const uint2*)&epg[row * D_ + 4 * c];
        __half2 h0 = *(__half2*)&u.x;
        __half2 h1 = *(__half2*)&u.y;
        float2 f0 = __half22float2(h0);
        float2 f1 = __half22float2(h1);
        *(float4*)&ep[row * EPS + 4 * c] = make_float4(f0.x, f0.y, f1.x, f1.y);
    }
    if (t < S_) {
        #pragma unroll
        for (int k = 0; k < 4; k++)
            pr[k * S_ + t] = g_probs[((size_t)(bb + 1024 * k) * H_ + h) * S_ + t];
    }
    __syncthreads();

    const int d = t & 127, gk = t >> 7;   // consumers k = gk and gk+2
    float a0 = 0.f, a1 = 0.f;
    const float* p0 = &pr[gk * S_];
    const float* p1 = &pr[(gk + 2) * S_];
    #pragma unroll 16
    for (int s = 0; s < S_; s++) {
        float ev = ep[s * EPS + d];
        a0 += p0[s] * ev;
        a1 += p1[s] * ev;
    }
    g_attn[(size_t)(bb + 1024 * gk) * 512 + h * D_ + d] = a0;
    g_attn[(size_t)(bb + 1024 * (gk + 2)) * 512 + h * D_ + d] = a1;
}

// ---------------------------------------------------------------------------
// MLP: register-blocked, broadcast float4 reads. 16 batches/block, 256 threads.
__global__ void __launch_bounds__(256) kMLP(
    const float* __restrict__ w3a, const float* __restrict__ b3a,
    const float* __restrict__ g3a, const float* __restrict__ be3a,
    const float* __restrict__ w3b, const float* __restrict__ b3b,
    const float* __restrict__ g3b, const float* __restrict__ be3b,
    float* __restrict__ out)
{
    __shared__ __align__(16) float as[16 * 512];
    __shared__ __align__(16) float h1[16 * D_];
    const int t = threadIdx.x;
    const int b0 = blockIdx.x * 16;
    const int d = t & 127, g = t >> 7;

    const float4* ap = (const float4*)(g_attn + (size_t)b0 * 512);
    float4* as4 = (float4*)as;
    #pragma unroll
    for (int j = 0; j < 8; j++) as4[t + 256 * j] = ap[t + 256 * j];
    __syncthreads();

    float acc[8];
    #pragma unroll
    for (int m = 0; m < 8; m++) acc[m] = 0.f;
    for (int i0 = 0; i0 < 512; i0 += 4) {
        float wv0 = w3a[(i0 + 0) * D_ + d];
        float wv1 = w3a[(i0 + 1) * D_ + d];
        float wv2 = w3a[(i0 + 2) * D_ + d];
        float wv3 = w3a[(i0 + 3) * D_ + d];
        #pragma unroll
        for (int m = 0; m < 8; m++) {
            float4 av = *(const float4*)&as[(g * 8 + m) * 512 + i0];
            acc[m] += av.x * wv0 + av.y * wv1 + av.z * wv2 + av.w * wv3;
        }
    }
    {
        float bb = b3a[d], gg = g3a[d], be = be3a[d];
        #pragma unroll
        for (int m = 0; m < 8; m++) {
            float v = (acc[m] + bb) * gg + be;
            h1[(g * 8 + m) * D_ + d] = fmaxf(v, 0.f);
        }
    }
    __syncthreads();

    #pragma unroll
    for (int m = 0; m < 8; m++) acc[m] = 0.f;
    for (int i0 = 0; i0 < D_; i0 += 4) {
        float wv0 = w3b[(i0 + 0) * D_ + d];
        float wv1 = w3b[(i0 + 1) * D_ + d];
        float wv2 = w3b[(i0 + 2) * D_ + d];
        float wv3 = w3b[(i0 + 3) * D_ + d];
        #pragma unroll
        for (int m = 0; m < 8; m++) {
            float4 hv = *(const float4*)&h1[(g * 8 + m) * D_ + i0];
            acc[m] += hv.x * wv0 + hv.y * wv1 + hv.z * wv2 + hv.w * wv3;
        }
    }
    {
        float bb = b3b[d], gg = g3b[d], be = be3b[d];
        #pragma unroll
        for (int m = 0; m < 8; m++) {
            float v = (acc[m] + bb) * gg + be;
            out[(size_t)(b0 + g * 8 + m) * D_ + d] = fmaxf(v, 0.f);
        }
    }
}

// ---------------------------------------------------------------------------
extern "C" void kernel_launch(void* const* d_in, const int* in_sizes, int n_in,
                              void* d_out, int out_size) {
    const float* x    = (const float*)d_in[0];
    const float* w_q  = (const float*)d_in[1];
    const float* b_q  = (const float*)d_in[2];
    const float* w_k  = (const float*)d_in[3];
    // d_in[4] = b_k: constant over s -> cancels in softmax. Unused.
    const float* w2   = (const float*)d_in[5];
    const float* b2   = (const float*)d_in[6];
    const float* w3a  = (const float*)d_in[7];
    const float* b3a  = (const float*)d_in[8];
    const float* g3a  = (const float*)d_in[9];
    const float* be3a = (const float*)d_in[10];
    const float* w3b  = (const float*)d_in[11];
    const float* b3b  = (const float*)d_in[12];
    const float* g3b  = (const float*)d_in[13];
    const float* be3b = (const float*)d_in[14];
    float* out = (float*)d_out;

    kSetup  <<<192, 128>>>(w_k);
    kMeanEP <<<B_, 256>>>(x);
    kChain  <<<B_ / 8, 256>>>(w_q, b_q, w2, b2);
    kScores <<<B_, 128>>>(0);
    kAttn   <<<B_, 256>>>(0);
    kMLP    <<<B_ / 16, 256>>>(w3a, b3a, g3a, be3a, w3b, b3b, g3b, be3b, out);
}

// round 6
// speedup vs baseline: 1.6160x; 1.0061x over previous
#include <cuda_runtime.h>
#include <cuda_fp16.h>
#include <math.h>

// TemporalAttentionEncoder — fp16 e_p staging, L2-resident passes 2/3.
//   kSetup  : pe table + w_k transpose
//   kMeanEP : e_p = x+pe -> fp16 (64MB, L2-resident); e_mean (fp32 exact)
//   kChain  : q_mean -> q_hat -> r  (b_k cancels in softmax)
//   kScores : probs = softmax( e_p16 . r / sqrt(32) )
//   kAttn   : attn[b,h] = probs[b,h] @ e_p16[(4b+h) mod B]   (torch tile quirk)
//   kMLP    : two Linear+BN+ReLU layers

#define B_   4096
#define S_   64
#define D_   128
#define H_   4
#define EPS  132   // fp32 smem row stride (conflict-free LDS.128 / STS.128 phases)

__device__ __align__(16) float  g_pe[S_ * D_];
__device__ __align__(16) float  g_wkT[D_ * D_];                 // wkT[c*128+d] = w_k[d*128+c]
__device__ __align__(16) __half g_ep16[(size_t)B_ * S_ * D_];   // 64 MB
__device__ __align__(16) float  g_emean[(size_t)B_ * D_];       // 2 MB
__device__ __align__(16) float  g_r[(size_t)B_ * H_ * D_];      // 8 MB
__device__ __align__(16) float  g_probs[(size_t)B_ * H_ * S_];  // 4 MB
__device__ __align__(16) float  g_attn[(size_t)B_ * H_ * D_];   // 8 MB

// ---------------------------------------------------------------------------
// Setup: blocks 0..63 build pe rows; blocks 64..191 transpose w_k row (b-64).
__global__ void kSetup(const float* __restrict__ w_k) {
    int b = blockIdx.x, t = threadIdx.x;
    if (b < 64) {
        int i = t >> 1;
        float freq = powf(1000.0f, -(float)i / 64.0f);
        float a = (float)b * freq;
        g_pe[b * D_ + t] = (t & 1) ? cosf(a) : sinf(a);
    } else {
        int d = b - 64;
        g_wkT[t * D_ + d] = w_k[d * D_ + t];
    }
}

// ---------------------------------------------------------------------------
// Pass 1: e_p -> fp16 global; e_mean (fp32). One block per batch, 256 threads.
__global__ void __launch_bounds__(256) kMeanEP(const float* __restrict__ x) {
    __shared__ __align__(16) float4 red[256];
    const int t = threadIdx.x, b = blockIdx.x;
    const int c = t & 31, r0 = t >> 5;
    const float4* xb  = (const float4*)(x + (size_t)b * (S_ * D_));
    const float4* pe4 = (const float4*)g_pe;

    float4 acc = make_float4(0.f, 0.f, 0.f, 0.f);
    #pragma unroll
    for (int j = 0; j < 8; j++) {
        int row = r0 + 8 * j;
        float4 v = xb[row * 32 + c];
        float4 p = __ldg(pe4 + row * 32 + c);
        v.x += p.x; v.y += p.y; v.z += p.z; v.w += p.w;
        acc.x += v.x; acc.y += v.y; acc.z += v.z; acc.w += v.w;
        __half2 h0 = __floats2half2_rn(v.x, v.y);
        __half2 h1 = __floats2half2_rn(v.z, v.w);
        uint2 u;
        u.x = *(unsigned int*)&h0;
        u.y = *(unsigned int*)&h1;
        *(uint2*)&g_ep16[((size_t)b * S_ + row) * D_ + 4 * c] = u;
    }
    red[r0 * 32 + c] = acc;
    __syncthreads();

    if (t < 32) {
        float4 s = red[t];
        #pragma unroll
        for (int r = 1; r < 8; r++) {
            float4 u = red[r * 32 + t];
            s.x += u.x; s.y += u.y; s.z += u.z; s.w += u.w;
        }
        const float inv = 1.0f / (float)S_;
        s.x *= inv; s.y *= inv; s.z *= inv; s.w *= inv;
        ((float4*)g_emean)[(size_t)b * 32 + t] = s;
    }
}

// ---------------------------------------------------------------------------
// Chain: q_mean = em@w_q+b_q ; q_hat = qm@w2+b2 ; r.  8 batches/block.
__global__ void __launch_bounds__(256) kChain(
    const float* __restrict__ w_q, const float* __restrict__ b_q,
    const float* __restrict__ w2,  const float* __restrict__ b2)
{
    __shared__ float em[8 * D_];
    __shared__ float qm[8 * D_];
    __shared__ float qh[8 * D_];
    const int t = threadIdx.x;
    const int b0 = blockIdx.x * 8;
    const int d = t & 127, g = t >> 7;

    #pragma unroll
    for (int j = 0; j < 4; j++) em[t + 256 * j] = g_emean[(size_t)b0 * D_ + t + 256 * j];
    __syncthreads();

    {
        float acc[4] = {0.f, 0.f, 0.f, 0.f};
        for (int j = 0; j < D_; j++) {
            float wv = w_q[j * D_ + d];
            #pragma unroll
            for (int m = 0; m < 4; m++) acc[m] += em[(g * 4 + m) * D_ + j] * wv;
        }
        float bq = b_q[d];
        #pragma unroll
        for (int m = 0; m < 4; m++) qm[(g * 4 + m) * D_ + d] = acc[m] + bq;
    }
    __syncthreads();
    {
        float acc[4] = {0.f, 0.f, 0.f, 0.f};
        for (int j = 0; j < D_; j++) {
            float wv = w2[j * D_ + d];
            #pragma unroll
            for (int m = 0; m < 4; m++) acc[m] += qm[(g * 4 + m) * D_ + j] * wv;
        }
        float bb = b2[d];
        #pragma unroll
        for (int m = 0; m < 4; m++) qh[(g * 4 + m) * D_ + d] = acc[m] + bb;
    }
    __syncthreads();
    #pragma unroll
    for (int h = 0; h < H_; h++) {
        float acc[4] = {0.f, 0.f, 0.f, 0.f};
        #pragma unroll 8
        for (int j = 0; j < 32; j++) {
            float wv = g_wkT[(h * 32 + j) * D_ + d];
            #pragma unroll
            for (int m = 0; m < 4; m++) acc[m] += qh[(g * 4 + m) * D_ + h * 32 + j] * wv;
        }
        #pragma unroll
        for (int m = 0; m < 4; m++)
            g_r[((size_t)(b0 + g * 4 + m) * H_ + h) * D_ + d] = acc[m];
    }
}

// ---------------------------------------------------------------------------
// Pass 2: scores + softmax from e_p16. One block per batch; 128 threads.
// Thread (g = t>>6, s = t&63) computes heads g and g+2, sharing each ep row read.
__global__ void __launch_bounds__(128) kScores(int dummy) {
    __shared__ __align__(16) float ep[S_ * EPS];   // ~33 KB fp32 tile
    __shared__ __align__(16) float rs[H_ * D_];    // 2 KB
    __shared__ float sc[H_ * S_];                  // 1 KB
    const int t = threadIdx.x, b = blockIdx.x;

    // Stage: 2048 uint2 chunks (4 halves) -> fp32 smem, conflict-free STS.128
    const __half* epg = g_ep16 + (size_t)b * (S_ * D_);
    #pragma unroll
    for (int j = 0; j < 16; j++) {
        int q = t + 128 * j;
        int row = q >> 5, c = q & 31;
        uint2 u = *(const uint2*)&epg[row * D_ + 4 * c];
        __half2 h0 = *(__half2*)&u.x;
        __half2 h1 = *(__half2*)&u.y;
        float2 f0 = __half22float2(h0);
        float2 f1 = __half22float2(h1);
        *(float4*)&ep[row * EPS + 4 * c] = make_float4(f0.x, f0.y, f1.x, f1.y);
    }
    ((float4*)rs)[t] = ((const float4*)(g_r + (size_t)b * (H_ * D_)))[t];
    __syncthreads();

    // scores: 2 heads per thread
    {
        const int g = t >> 6, s = t & 63;
        const float4* er = (const float4*)&ep[s * EPS];
        const float4* r0 = (const float4*)&rs[g * D_];
        const float4* r1 = (const float4*)&rs[(g + 2) * D_];
        float a0 = 0.f, a1 = 0.f;
        #pragma unroll 8
        for (int j = 0; j < 32; j++) {
            float4 e  = er[j];
            float4 w0 = r0[j];   // warp-uniform broadcast
            float4 w1 = r1[j];
            a0 += e.x * w0.x + e.y * w0.y + e.z * w0.z + e.w * w0.w;
            a1 += e.x * w1.x + e.y * w1.y + e.z * w1.z + e.w * w1.w;
        }
        const float scale = 0.17677669529663689f;  // 1/sqrt(32)
        sc[g * S_ + s]       = a0 * scale;
        sc[(g + 2) * S_ + s] = a1 * scale;
    }
    __syncthreads();

    // softmax: warp h handles head h; lane l owns entries l, l+32
    {
        int h = t >> 5, l = t & 31;
        const float* pp = &sc[h * S_];
        float v0 = pp[l], v1 = pp[32 + l];
        float mx = fmaxf(v0, v1);
        #pragma unroll
        for (int o = 16; o > 0; o >>= 1) mx = fmaxf(mx, __shfl_xor_sync(0xffffffffu, mx, o));
        float e0 = expf(v0 - mx), e1 = expf(v1 - mx);
        float sum = e0 + e1;
        #pragma unroll
        for (int o = 16; o > 0; o >>= 1) sum += __shfl_xor_sync(0xffffffffu, sum, o);
        float inv = 1.0f / sum;
        float* po = g_probs + ((size_t)b * H_ + h) * S_;
        po[l] = e0 * inv;
        po[32 + l] = e1 * inv;
    }
}

// ---------------------------------------------------------------------------
// Pass 3: attention from e_p16. One block per SOURCE batch j; 256 threads.
// Consumers b = (j>>2)+1024k on head h = j&3.
__global__ void __launch_bounds__(256) kAttn(int dummy) {
    __shared__ __align__(16) float ep[S_ * EPS];
    __shared__ float pr[4 * S_];
    const int t = threadIdx.x, j = blockIdx.x;
    const int h = j & 3, bb = j >> 2;

    const __half* epg = g_ep16 + (size_t)j * (S_ * D_);
    #pragma unroll
    for (int q0 = 0; q0 < 8; q0++) {
        int q = t + 256 * q0;
        int row = q >> 5, c = q & 31;
        uint2 u = *(const uint2*)&epg[row * D_ + 4 * c];
        __half2 h0 = *(__half2*)&u.x;
        __half2 h1 = *(__half2*)&u.y;
        float2 f0 = __half22float2(h0);
        float2 f1 = __half22float2(h1);
        *(float4*)&ep[row * EPS + 4 * c] = make_float4(f0.x, f0.y, f1.x, f1.y);
    }
    if (t < S_) {
        #pragma unroll
        for (int k = 0; k < 4; k++)
            pr[k * S_ + t] = g_probs[((size_t)(bb + 1024 * k) * H_ + h) * S_ + t];
    }
    __syncthreads();

    const int d = t & 127, gk = t >> 7;   // consumers k = gk and gk+2
    float a0 = 0.f, a1 = 0.f;
    const float* p0 = &pr[gk * S_];
    const float* p1 = &pr[(gk + 2) * S_];
    #pragma unroll 16
    for (int s = 0; s < S_; s++) {
        float ev = ep[s * EPS + d];
        a0 += p0[s] * ev;
        a1 += p1[s] * ev;
    }
    g_attn[(size_t)(bb + 1024 * gk) * 512 + h * D_ + d] = a0;
    g_attn[(size_t)(bb + 1024 * (gk + 2)) * 512 + h * D_ + d] = a1;
}

// ---------------------------------------------------------------------------
// MLP: register-blocked, broadcast float4 reads. 16 batches/block, 256 threads.
__global__ void __launch_bounds__(256) kMLP(
    const float* __restrict__ w3a, const float* __restrict__ b3a,
    const float* __restrict__ g3a, const float* __restrict__ be3a,
    const float* __restrict__ w3b, const float* __restrict__ b3b,
    const float* __restrict__ g3b, const float* __restrict__ be3b,
    float* __restrict__ out)
{
    __shared__ __align__(16) float as[16 * 512];
    __shared__ __align__(16) float h1[16 * D_];
    const int t = threadIdx.x;
    const int b0 = blockIdx.x * 16;
    const int d = t & 127, g = t >> 7;

    const float4* ap = (const float4*)(g_attn + (size_t)b0 * 512);
    float4* as4 = (float4*)as;
    #pragma unroll
    for (int j = 0; j < 8; j++) as4[t + 256 * j] = ap[t + 256 * j];
    __syncthreads();

    float acc[8];
    #pragma unroll
    for (int m = 0; m < 8; m++) acc[m] = 0.f;
    for (int i0 = 0; i0 < 512; i0 += 4) {
        float wv0 = w3a[(i0 + 0) * D_ + d];
        float wv1 = w3a[(i0 + 1) * D_ + d];
        float wv2 = w3a[(i0 + 2) * D_ + d];
        float wv3 = w3a[(i0 + 3) * D_ + d];
        #pragma unroll
        for (int m = 0; m < 8; m++) {
            float4 av = *(const float4*)&as[(g * 8 + m) * 512 + i0];
            acc[m] += av.x * wv0 + av.y * wv1 + av.z * wv2 + av.w * wv3;
        }
    }
    {
        float bb = b3a[d], gg = g3a[d], be = be3a[d];
        #pragma unroll
        for (int m = 0; m < 8; m++) {
            float v = (acc[m] + bb) * gg + be;
            h1[(g * 8 + m) * D_ + d] = fmaxf(v, 0.f);
        }
    }
    __syncthreads();

    #pragma unroll
    for (int m = 0; m < 8; m++) acc[m] = 0.f;
    for (int i0 = 0; i0 < D_; i0 += 4) {
        float wv0 = w3b[(i0 + 0) * D_ + d];
        float wv1 = w3b[(i0 + 1) * D_ + d];
        float wv2 = w3b[(i0 + 2) * D_ + d];
        float wv3 = w3b[(i0 + 3) * D_ + d];
        #pragma unroll
        for (int m = 0; m < 8; m++) {
            float4 hv = *(const float4*)&h1[(g * 8 + m) * D_ + i0];
            acc[m] += hv.x * wv0 + hv.y * wv1 + hv.z * wv2 + hv.w * wv3;
        }
    }
    {
        float bb = b3b[d], gg = g3b[d], be = be3b[d];
        #pragma unroll
        for (int m = 0; m < 8; m++) {
            float v = (acc[m] + bb) * gg + be;
            out[(size_t)(b0 + g * 8 + m) * D_ + d] = fmaxf(v, 0.f);
        }
    }
}

// ---------------------------------------------------------------------------
extern "C" void kernel_launch(void* const* d_in, const int* in_sizes, int n_in,
                              void* d_out, int out_size) {
    const float* x    = (const float*)d_in[0];
    const float* w_q  = (const float*)d_in[1];
    const float* b_q  = (const float*)d_in[2];
    const float* w_k  = (const float*)d_in[3];
    // d_in[4] = b_k: constant over s -> cancels in softmax. Unused.
    const float* w2   = (const float*)d_in[5];
    const float* b2   = (const float*)d_in[6];
    const float* w3a  = (const float*)d_in[7];
    const float* b3a  = (const float*)d_in[8];
    const float* g3a  = (const float*)d_in[9];
    const float* be3a = (const float*)d_in[10];
    const float* w3b  = (const float*)d_in[11];
    const float* b3b  = (const float*)d_in[12];
    const float* g3b  = (const float*)d_in[13];
    const float* be3b = (const float*)d_in[14];
    float* out = (float*)d_out;

    kSetup  <<<192, 128>>>(w_k);
    kMeanEP <<<B_, 256>>>(x);
    kChain  <<<B_ / 8, 256>>>(w_q, b_q, w2, b2);
    kScores <<<B_, 128>>>(0);
    kAttn   <<<B_, 256>>>(0);
    kMLP    <<<B_ / 16, 256>>>(w3a, b3a, g3a, be3a, w3b, b3b, g3b, be3b, out);
}

// round 8
// speedup vs baseline: 1.7041x; 1.0545x over previous
#include <cuda_runtime.h>
#include <cuda_fp16.h>
#include <math.h>

// TemporalAttentionEncoder — fp16 e_p staging; LDS-optimized scores/attn.
//   kSetup  : pe table + w_k transpose
//   kMeanEP : e_p = x+pe -> fp16 (64MB, L2-resident); e_mean (fp32 exact)
//   kChain  : q_mean -> q_hat -> r  (b_k cancels in softmax)
//   kScores : probs = softmax( e_p16 . r / sqrt(32) )   [fp16 smem, 1x tile read]
//   kAttn   : attn[b,h] = probs[b,h] @ e_p16[(4b+h) mod B]  [register streaming]
//   kMLP    : two Linear+BN+ReLU layers

#define B_   4096
#define S_   64
#define D_   128
#define H_   4

__device__ __align__(16) float  g_pe[S_ * D_];
__device__ __align__(16) float  g_wkT[D_ * D_];                 // wkT[c*128+d] = w_k[d*128+c]
__device__ __align__(16) __half g_ep16[(size_t)B_ * S_ * D_];   // 64 MB
__device__ __align__(16) float  g_emean[(size_t)B_ * D_];       // 2 MB
__device__ __align__(16) float  g_r[(size_t)B_ * H_ * D_];      // 8 MB
__device__ __align__(16) float  g_probs[(size_t)B_ * H_ * S_];  // 4 MB
__device__ __align__(16) float  g_attn[(size_t)B_ * H_ * D_];   // 8 MB

// ---------------------------------------------------------------------------
// Setup: blocks 0..63 build pe rows; blocks 64..191 transpose w_k row (b-64).
__global__ void kSetup(const float* __restrict__ w_k) {
    int b = blockIdx.x, t = threadIdx.x;
    if (b < 64) {
        int i = t >> 1;
        float freq = powf(1000.0f, -(float)i / 64.0f);
        float a = (float)b * freq;
        g_pe[b * D_ + t] = (t & 1) ? cosf(a) : sinf(a);
    } else {
        int d = b - 64;
        g_wkT[t * D_ + d] = w_k[d * D_ + t];
    }
}

// ---------------------------------------------------------------------------
// Pass 1: e_p -> fp16 global; e_mean (fp32). One block per batch, 256 threads.
__global__ void __launch_bounds__(256) kMeanEP(const float* __restrict__ x) {
    __shared__ __align__(16) float4 red[256];
    const int t = threadIdx.x, b = blockIdx.x;
    const int c = t & 31, r0 = t >> 5;
    const float4* xb  = (const float4*)(x + (size_t)b * (S_ * D_));
    const float4* pe4 = (const float4*)g_pe;

    float4 acc = make_float4(0.f, 0.f, 0.f, 0.f);
    #pragma unroll
    for (int j = 0; j < 8; j++) {
        int row = r0 + 8 * j;
        float4 v = xb[row * 32 + c];
        float4 p = __ldg(pe4 + row * 32 + c);
        v.x += p.x; v.y += p.y; v.z += p.z; v.w += p.w;
        acc.x += v.x; acc.y += v.y; acc.z += v.z; acc.w += v.w;
        __half2 h0 = __floats2half2_rn(v.x, v.y);
        __half2 h1 = __floats2half2_rn(v.z, v.w);
        uint2 u;
        u.x = *(unsigned int*)&h0;
        u.y = *(unsigned int*)&h1;
        *(uint2*)&g_ep16[((size_t)b * S_ + row) * D_ + 4 * c] = u;
    }
    red[r0 * 32 + c] = acc;
    __syncthreads();

    if (t < 32) {
        float4 s = red[t];
        #pragma unroll
        for (int r = 1; r < 8; r++) {
            float4 u = red[r * 32 + t];
            s.x += u.x; s.y += u.y; s.z += u.z; s.w += u.w;
        }
        const float inv = 1.0f / (float)S_;
        s.x *= inv; s.y *= inv; s.z *= inv; s.w *= inv;
        ((float4*)g_emean)[(size_t)b * 32 + t] = s;
    }
}

// ---------------------------------------------------------------------------
// Chain: q_mean = em@w_q+b_q ; q_hat = qm@w2+b2 ; r.  8 batches/block.
__global__ void __launch_bounds__(256) kChain(
    const float* __restrict__ w_q, const float* __restrict__ b_q,
    const float* __restrict__ w2,  const float* __restrict__ b2)
{
    __shared__ float em[8 * D_];
    __shared__ float qm[8 * D_];
    __shared__ float qh[8 * D_];
    const int t = threadIdx.x;
    const int b0 = blockIdx.x * 8;
    const int d = t & 127, g = t >> 7;

    #pragma unroll
    for (int j = 0; j < 4; j++) em[t + 256 * j] = g_emean[(size_t)b0 * D_ + t + 256 * j];
    __syncthreads();

    {
        float acc[4] = {0.f, 0.f, 0.f, 0.f};
        for (int j = 0; j < D_; j++) {
            float wv = w_q[j * D_ + d];
            #pragma unroll
            for (int m = 0; m < 4; m++) acc[m] += em[(g * 4 + m) * D_ + j] * wv;
        }
        float bq = b_q[d];
        #pragma unroll
        for (int m = 0; m < 4; m++) qm[(g * 4 + m) * D_ + d] = acc[m] + bq;
    }
    __syncthreads();
    {
        float acc[4] = {0.f, 0.f, 0.f, 0.f};
        for (int j = 0; j < D_; j++) {
            float wv = w2[j * D_ + d];
            #pragma unroll
            for (int m = 0; m < 4; m++) acc[m] += qm[(g * 4 + m) * D_ + j] * wv;
        }
        float bb = b2[d];
        #pragma unroll
        for (int m = 0; m < 4; m++) qh[(g * 4 + m) * D_ + d] = acc[m] + bb;
    }
    __syncthreads();
    #pragma unroll
    for (int h = 0; h < H_; h++) {
        float acc[4] = {0.f, 0.f, 0.f, 0.f};
        #pragma unroll 8
        for (int j = 0; j < 32; j++) {
            float wv = g_wkT[(h * 32 + j) * D_ + d];
            #pragma unroll
            for (int m = 0; m < 4; m++) acc[m] += qh[(g * 4 + m) * D_ + h * 32 + j] * wv;
        }
        #pragma unroll
        for (int m = 0; m < 4; m++)
            g_r[((size_t)(b0 + g * 4 + m) * H_ + h) * D_ + d] = acc[m];
    }
}

// ---------------------------------------------------------------------------
// Pass 2: scores + softmax. 2 batches per block, 128 threads.
// fp16 smem tile, row stride 136 halves (272B): conflict-free LDS.128 row reads.
// Thread (q = t>>6, s = t&63) computes ALL 4 heads for its row (tile read once).
__global__ void __launch_bounds__(128) kScores(int dummy) {
    __shared__ __align__(16) __half ep2[128 * 136];   // ~34 KB (2 tiles)
    __shared__ __align__(16) float rs[2 * H_ * D_];   // 4 KB
    __shared__ float sc[2 * H_ * S_];                 // 2 KB
    const int t = threadIdx.x;
    const int b0 = blockIdx.x * 2;

    // Stage 2 fp16 tiles: 4096 uint2 (4 halves each)
    #pragma unroll
    for (int j = 0; j < 32; j++) {
        int idx = t + 128 * j;
        int row = idx >> 5, c = idx & 31;   // row 0..127 (tile = row>>6), c 0..31
        uint2 u = *(const uint2*)&g_ep16[((size_t)b0 + (row >> 6)) * (S_ * D_)
                                         + (size_t)(row & 63) * D_ + 4 * c];
        *(uint2*)&ep2[row * 136 + 4 * c] = u;
    }
    #pragma unroll
    for (int j = 0; j < 2; j++)
        ((float4*)rs)[t + 128 * j] = ((const float4*)(g_r + (size_t)b0 * (H_ * D_)))[t + 128 * j];
    __syncthreads();

    // scores: 4 heads per thread, fp16 row read once
    {
        const int q = t >> 6, s = t & 63;
        const __half* er = &ep2[(q * 64 + s) * 136];
        const float* rq = &rs[q * (H_ * D_)];
        float acc[4] = {0.f, 0.f, 0.f, 0.f};
        #pragma unroll
        for (int j = 0; j < 16; j++) {
            uint4 u = *(const uint4*)&er[8 * j];
            __half2* hp = (__half2*)&u;
            float2 f0 = __half22float2(hp[0]);
            float2 f1 = __half22float2(hp[1]);
            float2 f2 = __half22float2(hp[2]);
            float2 f3 = __half22float2(hp[3]);
            #pragma unroll
            for (int h = 0; h < 4; h++) {
                float4 w0 = *(const float4*)&rq[h * D_ + 8 * j];      // broadcast
                float4 w1 = *(const float4*)&rq[h * D_ + 8 * j + 4];  // broadcast
                acc[h] += f0.x * w0.x + f0.y * w0.y + f1.x * w0.z + f1.y * w0.w
                        + f2.x * w1.x + f2.y * w1.y + f3.x * w1.z + f3.y * w1.w;
            }
        }
        const float scale = 0.17677669529663689f;  // 1/sqrt(32)
        #pragma unroll
        for (int h = 0; h < 4; h++) sc[(q * 4 + h) * S_ + s] = acc[h] * scale;
    }
    __syncthreads();

    // softmax: 8 jobs (q,h); warp w handles jobs 2w, 2w+1
    {
        const int w = t >> 5, l = t & 31;
        #pragma unroll
        for (int jj = 0; jj < 2; jj++) {
            int job = w * 2 + jj;              // = q*4 + h
            const float* pp = &sc[job * S_];
            float v0 = pp[l], v1 = pp[32 + l];
            float mx = fmaxf(v0, v1);
            #pragma unroll
            for (int o = 16; o > 0; o >>= 1) mx = fmaxf(mx, __shfl_xor_sync(0xffffffffu, mx, o));
            float e0 = expf(v0 - mx), e1 = expf(v1 - mx);
            float sum = e0 + e1;
            #pragma unroll
            for (int o = 16; o > 0; o >>= 1) sum += __shfl_xor_sync(0xffffffffu, sum, o);
            float inv = 1.0f / sum;
            float* po = g_probs + ((size_t)(b0 + (job >> 2)) * H_ + (job & 3)) * S_;
            po[l] = e0 * inv;
            po[32 + l] = e1 * inv;
        }
    }
}

// ---------------------------------------------------------------------------
// Pass 3: attention, register streaming (no ep smem tile).
// Block per SOURCE j; consumers b = (j>>2)+1024k, head h = j&3. 256 threads.
__global__ void __launch_bounds__(256) kAttn(int dummy) {
    __shared__ float pr[4 * S_];                        // 1 KB
    __shared__ __align__(16) float4 red[8 * 4 * 32];    // 16 KB
    const int t = threadIdx.x, j = blockIdx.x;
    const int h = j & 3, bb = j >> 2;

    {
        int k = t >> 6, row = t & 63;
        pr[k * S_ + row] = g_probs[((size_t)(bb + 1024 * k) * H_ + h) * S_ + row];
    }
    __syncthreads();

    const int c = t & 31, r0 = t >> 5;
    float4 acc[4];
    #pragma unroll
    for (int k = 0; k < 4; k++) acc[k] = make_float4(0.f, 0.f, 0.f, 0.f);

    const __half* epg = g_ep16 + (size_t)j * (S_ * D_);
    #pragma unroll
    for (int m = 0; m < 8; m++) {
        int row = r0 + 8 * m;
        uint2 u = *(const uint2*)&epg[row * D_ + 4 * c];
        __half2* hp = (__half2*)&u;
        float2 f0 = __half22float2(hp[0]);
        float2 f1 = __half22float2(hp[1]);
        #pragma unroll
        for (int k = 0; k < 4; k++) {
            float p = pr[k * S_ + row];   // warp-uniform broadcast
            acc[k].x += p * f0.x; acc[k].y += p * f0.y;
            acc[k].z += p * f1.x; acc[k].w += p * f1.y;
        }
    }
    #pragma unroll
    for (int k = 0; k < 4; k++) red[(r0 * 4 + k) * 32 + c] = acc[k];
    __syncthreads();

    if (t < 128) {
        const int k = t >> 5, cc = t & 31;
        float4 s = red[k * 32 + cc];
        #pragma unroll
        for (int r = 1; r < 8; r++) {
            float4 u = red[(r * 4 + k) * 32 + cc];
            s.x += u.x; s.y += u.y; s.z += u.z; s.w += u.w;
        }
        *(float4*)&g_attn[(size_t)(bb + 1024 * k) * 512 + h * D_ + 4 * cc] = s;
    }
}

// ---------------------------------------------------------------------------
// MLP: register-blocked, broadcast float4 reads. 16 batches/block, 256 threads.
__global__ void __launch_bounds__(256) kMLP(
    const float* __restrict__ w3a, const float* __restrict__ b3a,
    const float* __restrict__ g3a, const float* __restrict__ be3a,
    const float* __restrict__ w3b, const float* __restrict__ b3b,
    const float* __restrict__ g3b, const float* __restrict__ be3b,
    float* __restrict__ out)
{
    __shared__ __align__(16) float as[16 * 512];
    __shared__ __align__(16) float h1[16 * D_];
    const int t = threadIdx.x;
    const int b0 = blockIdx.x * 16;
    const int d = t & 127, g = t >> 7;

    const float4* ap = (const float4*)(g_attn + (size_t)b0 * 512);
    float4* as4 = (float4*)as;
    #pragma unroll
    for (int j = 0; j < 8; j++) as4[t + 256 * j] = ap[t + 256 * j];
    __syncthreads();

    float acc[8];
    #pragma unroll
    for (int m = 0; m < 8; m++) acc[m] = 0.f;
    for (int i0 = 0; i0 < 512; i0 += 4) {
        float wv0 = w3a[(i0 + 0) * D_ + d];
        float wv1 = w3a[(i0 + 1) * D_ + d];
        float wv2 = w3a[(i0 + 2) * D_ + d];
        float wv3 = w3a[(i0 + 3) * D_ + d];
        #pragma unroll
        for (int m = 0; m < 8; m++) {
            float4 av = *(const float4*)&as[(g * 8 + m) * 512 + i0];
            acc[m] += av.x * wv0 + av.y * wv1 + av.z * wv2 + av.w * wv3;
        }
    }
    {
        float bb = b3a[d], gg = g3a[d], be = be3a[d];
        #pragma unroll
        for (int m = 0; m < 8; m++) {
            float v = (acc[m] + bb) * gg + be;
            h1[(g * 8 + m) * D_ + d] = fmaxf(v, 0.f);
        }
    }
    __syncthreads();

    #pragma unroll
    for (int m = 0; m < 8; m++) acc[m] = 0.f;
    for (int i0 = 0; i0 < D_; i0 += 4) {
        float wv0 = w3b[(i0 + 0) * D_ + d];
        float wv1 = w3b[(i0 + 1) * D_ + d];
        float wv2 = w3b[(i0 + 2) * D_ + d];
        float wv3 = w3b[(i0 + 3) * D_ + d];
        #pragma unroll
        for (int m = 0; m < 8; m++) {
            float4 hv = *(const float4*)&h1[(g * 8 + m) * D_ + i0];
            acc[m] += hv.x * wv0 + hv.y * wv1 + hv.z * wv2 + hv.w * wv3;
        }
    }
    {
        float bb = b3b[d], gg = g3b[d], be = be3b[d];
        #pragma unroll
        for (int m = 0; m < 8; m++) {
            float v = (acc[m] + bb) * gg + be;
            out[(size_t)(b0 + g * 8 + m) * D_ + d] = fmaxf(v, 0.f);
        }
    }
}

// ---------------------------------------------------------------------------
extern "C" void kernel_launch(void* const* d_in, const int* in_sizes, int n_in,
                              void* d_out, int out_size) {
    const float* x    = (const float*)d_in[0];
    const float* w_q  = (const float*)d_in[1];
    const float* b_q  = (const float*)d_in[2];
    const float* w_k  = (const float*)d_in[3];
    // d_in[4] = b_k: constant over s -> cancels in softmax. Unused.
    const float* w2   = (const float*)d_in[5];
    const float* b2   = (const float*)d_in[6];
    const float* w3a  = (const float*)d_in[7];
    const float* b3a  = (const float*)d_in[8];
    const float* g3a  = (const float*)d_in[9];
    const float* be3a = (const float*)d_in[10];
    const float* w3b  = (const float*)d_in[11];
    const float* b3b  = (const float*)d_in[12];
    const float* g3b  = (const float*)d_in[13];
    const float* be3b = (const float*)d_in[14];
    float* out = (float*)d_out;

    kSetup  <<<192, 128>>>(w_k);
    kMeanEP <<<B_, 256>>>(x);
    kChain  <<<B_ / 8, 256>>>(w_q, b_q, w2, b2);
    kScores <<<B_ / 2, 128>>>(0);
    kAttn   <<<B_, 256>>>(0);
    kMLP    <<<B_ / 16, 256>>>(w3a, b3a, g3a, be3a, w3b, b3b, g3b, be3b, out);
}

// round 9
// speedup vs baseline: 1.7207x; 1.0097x over previous
#include <cuda_runtime.h>
#include <cuda_fp16.h>
#include <math.h>

// TemporalAttentionEncoder — fp16 e_p staging; fused chain+scores (warp-streaming).
//   kSetup  : pe table + w_k transpose
//   kMeanEP : e_p = x+pe -> fp16 (64MB, L2-resident); e_mean (fp32 exact)
//   kCS     : per 8 batches: q chain -> r (smem) ; warp-per-batch scores+softmax
//             streaming e_p16 from L2 (no smem tile). b_k cancels in softmax.
//   kAttn   : attn[b,h] = probs[b,h] @ e_p16[(4b+h) mod B]  [register streaming]
//   kMLP    : two Linear+BN+ReLU layers

#define B_   4096
#define S_   64
#define D_   128
#define H_   4

__device__ __align__(16) float  g_pe[S_ * D_];
__device__ __align__(16) float  g_wkT[D_ * D_];                 // wkT[c*128+d] = w_k[d*128+c]
__device__ __align__(16) __half g_ep16[(size_t)B_ * S_ * D_];   // 64 MB
__device__ __align__(16) float  g_emean[(size_t)B_ * D_];       // 2 MB
__device__ __align__(16) float  g_probs[(size_t)B_ * H_ * S_];  // 4 MB
__device__ __align__(16) float  g_attn[(size_t)B_ * H_ * D_];   // 8 MB

// ---------------------------------------------------------------------------
// Setup: blocks 0..63 build pe rows; blocks 64..191 transpose w_k row (b-64).
__global__ void kSetup(const float* __restrict__ w_k) {
    int b = blockIdx.x, t = threadIdx.x;
    if (b < 64) {
        int i = t >> 1;
        float freq = powf(1000.0f, -(float)i / 64.0f);
        float a = (float)b * freq;
        g_pe[b * D_ + t] = (t & 1) ? cosf(a) : sinf(a);
    } else {
        int d = b - 64;
        g_wkT[t * D_ + d] = w_k[d * D_ + t];
    }
}

// ---------------------------------------------------------------------------
// Pass 1: e_p -> fp16 global; e_mean (fp32). One block per batch, 256 threads.
__global__ void __launch_bounds__(256) kMeanEP(const float* __restrict__ x) {
    __shared__ __align__(16) float4 red[256];
    const int t = threadIdx.x, b = blockIdx.x;
    const int c = t & 31, r0 = t >> 5;
    const float4* xb  = (const float4*)(x + (size_t)b * (S_ * D_));
    const float4* pe4 = (const float4*)g_pe;

    float4 acc = make_float4(0.f, 0.f, 0.f, 0.f);
    #pragma unroll
    for (int j = 0; j < 8; j++) {
        int row = r0 + 8 * j;
        float4 v = xb[row * 32 + c];
        float4 p = __ldg(pe4 + row * 32 + c);
        v.x += p.x; v.y += p.y; v.z += p.z; v.w += p.w;
        acc.x += v.x; acc.y += v.y; acc.z += v.z; acc.w += v.w;
        __half2 h0 = __floats2half2_rn(v.x, v.y);
        __half2 h1 = __floats2half2_rn(v.z, v.w);
        uint2 u;
        u.x = *(unsigned int*)&h0;
        u.y = *(unsigned int*)&h1;
        *(uint2*)&g_ep16[((size_t)b * S_ + row) * D_ + 4 * c] = u;
    }
    red[r0 * 32 + c] = acc;
    __syncthreads();

    if (t < 32) {
        float4 s = red[t];
        #pragma unroll
        for (int r = 1; r < 8; r++) {
            float4 u = red[r * 32 + t];
            s.x += u.x; s.y += u.y; s.z += u.z; s.w += u.w;
        }
        const float inv = 1.0f / (float)S_;
        s.x *= inv; s.y *= inv; s.z *= inv; s.w *= inv;
        ((float4*)g_emean)[(size_t)b * 32 + t] = s;
    }
}

// ---------------------------------------------------------------------------
// Fused chain + scores + softmax.  8 batches/block, 256 threads (8 warps).
// Chain phase: block-cooperative (em->qm->qh->r in smem).
// Scores phase: warp w owns batch b0+w; streams e_p16 rows from L2;
//   lane layout: rg = lane>>3 (row in 4-row group), u = lane&7 (d-chunk);
//   lane covers d = u*4 + 32k (k=0..3); 3-round shfl_xor reduce per row.
__global__ void __launch_bounds__(256) kCS(
    const float* __restrict__ w_q, const float* __restrict__ b_q,
    const float* __restrict__ w2,  const float* __restrict__ b2)
{
    __shared__ float chainbuf[3 * 1024];          // em | qm | qh ; sc aliases first 2KB*4
    __shared__ __align__(16) float rs[8 * H_ * D_];  // 16 KB: rs[(k*4+h)*128+d]
    float* em = chainbuf;
    float* qm = chainbuf + 1024;
    float* qh = chainbuf + 2048;
    float* sc = chainbuf;                          // 8*4*64 = 2048 floats, alias em/qm

    const int t = threadIdx.x;
    const int b0 = blockIdx.x * 8;
    const int d = t & 127, g = t >> 7;

    // ---- chain (block-cooperative over 8 batches) ----
    #pragma unroll
    for (int j = 0; j < 4; j++) em[t + 256 * j] = g_emean[(size_t)b0 * D_ + t + 256 * j];
    __syncthreads();

    {
        float acc[4] = {0.f, 0.f, 0.f, 0.f};
        for (int j = 0; j < D_; j++) {
            float wv = w_q[j * D_ + d];
            #pragma unroll
            for (int m = 0; m < 4; m++) acc[m] += em[(g * 4 + m) * D_ + j] * wv;
        }
        float bq = b_q[d];
        #pragma unroll
        for (int m = 0; m < 4; m++) qm[(g * 4 + m) * D_ + d] = acc[m] + bq;
    }
    __syncthreads();
    {
        float acc[4] = {0.f, 0.f, 0.f, 0.f};
        for (int j = 0; j < D_; j++) {
            float wv = w2[j * D_ + d];
            #pragma unroll
            for (int m = 0; m < 4; m++) acc[m] += qm[(g * 4 + m) * D_ + j] * wv;
        }
        float bb = b2[d];
        #pragma unroll
        for (int m = 0; m < 4; m++) qh[(g * 4 + m) * D_ + d] = acc[m] + bb;
    }
    __syncthreads();
    #pragma unroll
    for (int h = 0; h < H_; h++) {
        float acc[4] = {0.f, 0.f, 0.f, 0.f};
        #pragma unroll 8
        for (int j = 0; j < 32; j++) {
            float wv = g_wkT[(h * 32 + j) * D_ + d];
            #pragma unroll
            for (int m = 0; m < 4; m++) acc[m] += qh[(g * 4 + m) * D_ + h * 32 + j] * wv;
        }
        #pragma unroll
        for (int m = 0; m < 4; m++) rs[((g * 4 + m) * 4 + h) * D_ + d] = acc[m];
    }
    __syncthreads();   // rs ready; em/qm now dead -> sc alias safe

    // ---- scores (warp-autonomous, batch = b0 + w) ----
    const int w = t >> 5, lane = t & 31;
    const int rg = lane >> 3, u = lane & 7;
    const __half* epg = g_ep16 + (size_t)(b0 + w) * (S_ * D_);
    const float scale = 0.17677669529663689f;  // 1/sqrt(32)

    #pragma unroll 4
    for (int iter = 0; iter < 16; iter++) {
        const int s = iter * 4 + rg;
        const __half* ebase = epg + s * D_ + u * 4;
        float acc[4] = {0.f, 0.f, 0.f, 0.f};
        #pragma unroll
        for (int k = 0; k < 4; k++) {
            uint2 uu = *(const uint2*)(ebase + 32 * k);
            __half2* hp = (__half2*)&uu;
            float2 f0 = __half22float2(hp[0]);
            float2 f1 = __half22float2(hp[1]);
            #pragma unroll
            for (int h = 0; h < 4; h++) {
                float4 rv = *(const float4*)&rs[(w * 4 + h) * D_ + u * 4 + 32 * k];
                acc[h] += f0.x * rv.x + f0.y * rv.y + f1.x * rv.z + f1.y * rv.w;
            }
        }
        #pragma unroll
        for (int o = 1; o < 8; o <<= 1) {
            #pragma unroll
            for (int h = 0; h < 4; h++)
                acc[h] += __shfl_xor_sync(0xffffffffu, acc[h], o);
        }
        if (u == 0) {
            #pragma unroll
            for (int h = 0; h < 4; h++)
                sc[w * 256 + h * 64 + s] = acc[h] * scale;
        }
    }
    __syncwarp();

    // ---- softmax (warp-local), write probs ----
    #pragma unroll
    for (int h = 0; h < 4; h++) {
        float v0 = sc[w * 256 + h * 64 + lane];
        float v1 = sc[w * 256 + h * 64 + 32 + lane];
        float mx = fmaxf(v0, v1);
        #pragma unroll
        for (int o = 16; o > 0; o >>= 1) mx = fmaxf(mx, __shfl_xor_sync(0xffffffffu, mx, o));
        float e0 = expf(v0 - mx), e1 = expf(v1 - mx);
        float sum = e0 + e1;
        #pragma unroll
        for (int o = 16; o > 0; o >>= 1) sum += __shfl_xor_sync(0xffffffffu, sum, o);
        float inv = 1.0f / sum;
        float* po = g_probs + ((size_t)(b0 + w) * H_ + h) * S_;
        po[lane] = e0 * inv;
        po[32 + lane] = e1 * inv;
    }
}

// ---------------------------------------------------------------------------
// Pass 3: attention, register streaming (no ep smem tile).
// Block per SOURCE j; consumers b = (j>>2)+1024k, head h = j&3. 256 threads.
__global__ void __launch_bounds__(256) kAttn(int dummy) {
    __shared__ float pr[4 * S_];                        // 1 KB
    __shared__ __align__(16) float4 red[8 * 4 * 32];    // 16 KB
    const int t = threadIdx.x, j = blockIdx.x;
    const int h = j & 3, bb = j >> 2;

    {
        int k = t >> 6, row = t & 63;
        pr[k * S_ + row] = g_probs[((size_t)(bb + 1024 * k) * H_ + h) * S_ + row];
    }
    __syncthreads();

    const int c = t & 31, r0 = t >> 5;
    float4 acc[4];
    #pragma unroll
    for (int k = 0; k < 4; k++) acc[k] = make_float4(0.f, 0.f, 0.f, 0.f);

    const __half* epg = g_ep16 + (size_t)j * (S_ * D_);
    #pragma unroll
    for (int m = 0; m < 8; m++) {
        int row = r0 + 8 * m;
        uint2 u = *(const uint2*)&epg[row * D_ + 4 * c];
        __half2* hp = (__half2*)&u;
        float2 f0 = __half22float2(hp[0]);
        float2 f1 = __half22float2(hp[1]);
        #pragma unroll
        for (int k = 0; k < 4; k++) {
            float p = pr[k * S_ + row];   // warp-uniform broadcast
            acc[k].x += p * f0.x; acc[k].y += p * f0.y;
            acc[k].z += p * f1.x; acc[k].w += p * f1.y;
        }
    }
    #pragma unroll
    for (int k = 0; k < 4; k++) red[(r0 * 4 + k) * 32 + c] = acc[k];
    __syncthreads();

    if (t < 128) {
        const int k = t >> 5, cc = t & 31;
        float4 s = red[k * 32 + cc];
        #pragma unroll
        for (int r = 1; r < 8; r++) {
            float4 u = red[(r * 4 + k) * 32 + cc];
            s.x += u.x; s.y += u.y; s.z += u.z; s.w += u.w;
        }
        *(float4*)&g_attn[(size_t)(bb + 1024 * k) * 512 + h * D_ + 4 * cc] = s;
    }
}

// ---------------------------------------------------------------------------
// MLP: register-blocked, broadcast float4 reads. 8 batches/block, 256 threads.
__global__ void __launch_bounds__(256) kMLP(
    const float* __restrict__ w3a, const float* __restrict__ b3a,
    const float* __restrict__ g3a, const float* __restrict__ be3a,
    const float* __restrict__ w3b, const float* __restrict__ b3b,
    const float* __restrict__ g3b, const float* __restrict__ be3b,
    float* __restrict__ out)
{
    __shared__ __align__(16) float as[8 * 512];   // 16 KB
    __shared__ __align__(16) float h1[8 * D_];    // 4 KB
    const int t = threadIdx.x;
    const int b0 = blockIdx.x * 8;
    const int d = t & 127, g = t >> 7;

    const float4* ap = (const float4*)(g_attn + (size_t)b0 * 512);
    float4* as4 = (float4*)as;
    #pragma unroll
    for (int j = 0; j < 4; j++) as4[t + 256 * j] = ap[t + 256 * j];
    __syncthreads();

    float acc[4];
    #pragma unroll
    for (int m = 0; m < 4; m++) acc[m] = 0.f;
    for (int i0 = 0; i0 < 512; i0 += 4) {
        float wv0 = w3a[(i0 + 0) * D_ + d];
        float wv1 = w3a[(i0 + 1) * D_ + d];
        float wv2 = w3a[(i0 + 2) * D_ + d];
        float wv3 = w3a[(i0 + 3) * D_ + d];
        #pragma unroll
        for (int m = 0; m < 4; m++) {
            float4 av = *(const float4*)&as[(g * 4 + m) * 512 + i0];  // broadcast
            acc[m] += av.x * wv0 + av.y * wv1 + av.z * wv2 + av.w * wv3;
        }
    }
    {
        float bb = b3a[d], gg = g3a[d], be = be3a[d];
        #pragma unroll
        for (int m = 0; m < 4; m++) {
            float v = (acc[m] + bb) * gg + be;
            h1[(g * 4 + m) * D_ + d] = fmaxf(v, 0.f);
        }
    }
    __syncthreads();

    #pragma unroll
    for (int m = 0; m < 4; m++) acc[m] = 0.f;
    for (int i0 = 0; i0 < D_; i0 += 4) {
        float wv0 = w3b[(i0 + 0) * D_ + d];
        float wv1 = w3b[(i0 + 1) * D_ + d];
        float wv2 = w3b[(i0 + 2) * D_ + d];
        float wv3 = w3b[(i0 + 3) * D_ + d];
        #pragma unroll
        for (int m = 0; m < 4; m++) {
            float4 hv = *(const float4*)&h1[(g * 4 + m) * D_ + i0];
            acc[m] += hv.x * wv0 + hv.y * wv1 + hv.z * wv2 + hv.w * wv3;
        }
    }
    {
        float bb = b3b[d], gg = g3b[d], be = be3b[d];
        #pragma unroll
        for (int m = 0; m < 4; m++) {
            float v = (acc[m] + bb) * gg + be;
            out[(size_t)(b0 + g * 4 + m) * D_ + d] = fmaxf(v, 0.f);
        }
    }
}

// ---------------------------------------------------------------------------
extern "C" void kernel_launch(void* const* d_in, const int* in_sizes, int n_in,
                              void* d_out, int out_size) {
    const float* x    = (const float*)d_in[0];
    const float* w_q  = (const float*)d_in[1];
    const float* b_q  = (const float*)d_in[2];
    const float* w_k  = (const float*)d_in[3];
    // d_in[4] = b_k: constant over s -> cancels in softmax. Unused.
    const float* w2   = (const float*)d_in[5];
    const float* b2   = (const float*)d_in[6];
    const float* w3a  = (const float*)d_in[7];
    const float* b3a  = (const float*)d_in[8];
    const float* g3a  = (const float*)d_in[9];
    const float* be3a = (const float*)d_in[10];
    const float* w3b  = (const float*)d_in[11];
    const float* b3b  = (const float*)d_in[12];
    const float* g3b  = (const float*)d_in[13];
    const float* be3b = (const float*)d_in[14];
    float* out = (float*)d_out;

    kSetup  <<<192, 128>>>(w_k);
    kMeanEP <<<B_, 256>>>(x);
    kCS     <<<B_ / 8, 256>>>(w_q, b_q, w2, b2);
    kAttn   <<<B_, 256>>>(0);
    kMLP    <<<B_ / 8, 256>>>(w3a, b3a, g3a, be3a, w3b, b3b, g3b, be3b, out);
}

// round 10
// speedup vs baseline: 2.1457x; 1.2470x over previous
#include <cuda_runtime.h>
#include <cuda_fp16.h>
#include <math.h>

// TemporalAttentionEncoder — 3 launches.
//   kMeanEP  : e_p = x+pe -> fp16 (pe inline via sincosf); e_mean; piggybacked
//              w_k transpose (blocks 0..127).
//   kCS      : per 8 batches: q chain -> r (smem); warp-per-batch scores+softmax
//              streaming e_p16 from L2. b_k cancels in softmax.
//   kAttnMLP : block owns sources 8bi..8bi+7 -> 8 consumers complete (all heads);
//              attn in smem, MLP fused (no g_attn round-trip).

#define B_   4096
#define S_   64
#define D_   128
#define H_   4

__device__ __align__(16) float  g_wkT[D_ * D_];                 // wkT[c*128+d] = w_k[d*128+c]
__device__ __align__(16) __half g_ep16[(size_t)B_ * S_ * D_];   // 64 MB
__device__ __align__(16) float  g_emean[(size_t)B_ * D_];       // 2 MB
__device__ __align__(16) float  g_probs[(size_t)B_ * H_ * S_];  // 4 MB

// ---------------------------------------------------------------------------
// Pass 1: e_p -> fp16 global; e_mean (fp32). One block per batch, 256 threads.
// pe computed inline: thread covers dims 4c..4c+3 -> freq pairs i=2c, 2c+1.
// Blocks 0..127 also transpose w_k row b into g_wkT (consumed by kCS next).
__global__ void __launch_bounds__(256) kMeanEP(const float* __restrict__ x,
                                               const float* __restrict__ w_k) {
    __shared__ __align__(16) float4 red[256];
    const int t = threadIdx.x, b = blockIdx.x;
    const int c = t & 31, r0 = t >> 5;

    if (b < D_ && t < D_) g_wkT[t * D_ + b] = w_k[b * D_ + t];

    const float f0 = powf(1000.0f, -(float)(2 * c) / 64.0f);
    const float f1 = powf(1000.0f, -(float)(2 * c + 1) / 64.0f);

    const float4* xb = (const float4*)(x + (size_t)b * (S_ * D_));

    float4 acc = make_float4(0.f, 0.f, 0.f, 0.f);
    #pragma unroll
    for (int j = 0; j < 8; j++) {
        int row = r0 + 8 * j;
        float4 v = xb[row * 32 + c];
        float s0, c0, s1, c1;
        sincosf((float)row * f0, &s0, &c0);
        sincosf((float)row * f1, &s1, &c1);
        v.x += s0; v.y += c0; v.z += s1; v.w += c1;
        acc.x += v.x; acc.y += v.y; acc.z += v.z; acc.w += v.w;
        __half2 h0 = __floats2half2_rn(v.x, v.y);
        __half2 h1 = __floats2half2_rn(v.z, v.w);
        uint2 u;
        u.x = *(unsigned int*)&h0;
        u.y = *(unsigned int*)&h1;
        *(uint2*)&g_ep16[((size_t)b * S_ + row) * D_ + 4 * c] = u;
    }
    red[r0 * 32 + c] = acc;
    __syncthreads();

    if (t < 32) {
        float4 s = red[t];
        #pragma unroll
        for (int r = 1; r < 8; r++) {
            float4 u = red[r * 32 + t];
            s.x += u.x; s.y += u.y; s.z += u.z; s.w += u.w;
        }
        const float inv = 1.0f / (float)S_;
        s.x *= inv; s.y *= inv; s.z *= inv; s.w *= inv;
        ((float4*)g_emean)[(size_t)b * 32 + t] = s;
    }
}

// ---------------------------------------------------------------------------
// Fused chain + scores + softmax.  8 batches/block, 256 threads (8 warps).
__global__ void __launch_bounds__(256) kCS(
    const float* __restrict__ w_q, const float* __restrict__ b_q,
    const float* __restrict__ w2,  const float* __restrict__ b2)
{
    __shared__ float chainbuf[3 * 1024];             // em | qm | qh ; sc aliases
    __shared__ __align__(16) float rs[8 * H_ * D_];  // 16 KB: rs[(k*4+h)*128+d]
    float* em = chainbuf;
    float* qm = chainbuf + 1024;
    float* qh = chainbuf + 2048;
    float* sc = chainbuf;                            // 2048 floats, alias em/qm

    const int t = threadIdx.x;
    const int b0 = blockIdx.x * 8;
    const int d = t & 127, g = t >> 7;

    #pragma unroll
    for (int j = 0; j < 4; j++) em[t + 256 * j] = g_emean[(size_t)b0 * D_ + t + 256 * j];
    __syncthreads();

    {
        float acc[4] = {0.f, 0.f, 0.f, 0.f};
        for (int j = 0; j < D_; j++) {
            float wv = w_q[j * D_ + d];
            #pragma unroll
            for (int m = 0; m < 4; m++) acc[m] += em[(g * 4 + m) * D_ + j] * wv;
        }
        float bq = b_q[d];
        #pragma unroll
        for (int m = 0; m < 4; m++) qm[(g * 4 + m) * D_ + d] = acc[m] + bq;
    }
    __syncthreads();
    {
        float acc[4] = {0.f, 0.f, 0.f, 0.f};
        for (int j = 0; j < D_; j++) {
            float wv = w2[j * D_ + d];
            #pragma unroll
            for (int m = 0; m < 4; m++) acc[m] += qm[(g * 4 + m) * D_ + j] * wv;
        }
        float bb = b2[d];
        #pragma unroll
        for (int m = 0; m < 4; m++) qh[(g * 4 + m) * D_ + d] = acc[m] + bb;
    }
    __syncthreads();
    #pragma unroll
    for (int h = 0; h < H_; h++) {
        float acc[4] = {0.f, 0.f, 0.f, 0.f};
        #pragma unroll 8
        for (int j = 0; j < 32; j++) {
            float wv = g_wkT[(h * 32 + j) * D_ + d];
            #pragma unroll
            for (int m = 0; m < 4; m++) acc[m] += qh[(g * 4 + m) * D_ + h * 32 + j] * wv;
        }
        #pragma unroll
        for (int m = 0; m < 4; m++) rs[((g * 4 + m) * 4 + h) * D_ + d] = acc[m];
    }
    __syncthreads();   // rs ready; em/qm dead -> sc alias safe

    // scores (warp-autonomous, batch = b0 + w)
    const int w = t >> 5, lane = t & 31;
    const int rg = lane >> 3, u = lane & 7;
    const __half* epg = g_ep16 + (size_t)(b0 + w) * (S_ * D_);
    const float scale = 0.17677669529663689f;  // 1/sqrt(32)

    #pragma unroll 4
    for (int iter = 0; iter < 16; iter++) {
        const int s = iter * 4 + rg;
        const __half* ebase = epg + s * D_ + u * 4;
        float acc[4] = {0.f, 0.f, 0.f, 0.f};
        #pragma unroll
        for (int k = 0; k < 4; k++) {
            uint2 uu = *(const uint2*)(ebase + 32 * k);
            __half2* hp = (__half2*)&uu;
            float2 f0 = __half22float2(hp[0]);
            float2 f1 = __half22float2(hp[1]);
            #pragma unroll
            for (int h = 0; h < 4; h++) {
                float4 rv = *(const float4*)&rs[(w * 4 + h) * D_ + u * 4 + 32 * k];
                acc[h] += f0.x * rv.x + f0.y * rv.y + f1.x * rv.z + f1.y * rv.w;
            }
        }
        #pragma unroll
        for (int o = 1; o < 8; o <<= 1) {
            #pragma unroll
            for (int h = 0; h < 4; h++)
                acc[h] += __shfl_xor_sync(0xffffffffu, acc[h], o);
        }
        if (u == 0) {
            #pragma unroll
            for (int h = 0; h < 4; h++)
                sc[w * 256 + h * 64 + s] = acc[h] * scale;
        }
    }
    __syncwarp();

    #pragma unroll
    for (int h = 0; h < 4; h++) {
        float v0 = sc[w * 256 + h * 64 + lane];
        float v1 = sc[w * 256 + h * 64 + 32 + lane];
        float mx = fmaxf(v0, v1);
        #pragma unroll
        for (int o = 16; o > 0; o >>= 1) mx = fmaxf(mx, __shfl_xor_sync(0xffffffffu, mx, o));
        float e0 = expf(v0 - mx), e1 = expf(v1 - mx);
        float sum = e0 + e1;
        #pragma unroll
        for (int o = 16; o > 0; o >>= 1) sum += __shfl_xor_sync(0xffffffffu, sum, o);
        float inv = 1.0f / sum;
        float* po = g_probs + ((size_t)(b0 + w) * H_ + h) * S_;
        po[lane] = e0 * inv;
        po[32 + lane] = e1 * inv;
    }
}

// ---------------------------------------------------------------------------
// Fused attention + MLP.  Block bi owns sources 8bi..8bi+7 (2 consumer groups),
// i.e. consumers b = 2bi+q + 1024k (q=0..1, k=0..3), ALL heads -> attn complete
// in smem, then MLP. 256 threads.
__global__ void __launch_bounds__(256) kAttnMLP(
    const float* __restrict__ w3a, const float* __restrict__ b3a,
    const float* __restrict__ g3a, const float* __restrict__ be3a,
    const float* __restrict__ w3b, const float* __restrict__ b3b,
    const float* __restrict__ g3b, const float* __restrict__ be3b,
    float* __restrict__ out)
{
    __shared__ float pr[2048];                       // 8 KB  pr[q][k][h][s]
    __shared__ __align__(16) float4 red[1024];       // 16 KB reduce buf / h1 alias
    __shared__ __align__(16) float as[8 * 512];      // 16 KB attn rows [q*4+k][512]
    float* h1 = (float*)red;                         // 8*128 floats after attn phase

    const int t = threadIdx.x, bi = blockIdx.x;
    const int c = t & 31, r0 = t >> 5;

    // stage probs for 8 consumers x 4 heads
    #pragma unroll
    for (int z0 = 0; z0 < 8; z0++) {
        int z = t + 256 * z0;
        int q = z >> 10, k = (z >> 8) & 3, h = (z >> 6) & 3, s = z & 63;
        int b = 2 * bi + q + 1024 * k;
        pr[z] = g_probs[((size_t)b * H_ + h) * S_ + s];
    }
    __syncthreads();

    // attention: 8 source tiles j = 8bi + 4q + h
    #pragma unroll
    for (int q = 0; q < 2; q++) {
        #pragma unroll
        for (int h = 0; h < H_; h++) {
            const int j = 8 * bi + 4 * q + h;
            const __half* epg = g_ep16 + (size_t)j * (S_ * D_);
            float4 acc[4];
            #pragma unroll
            for (int k = 0; k < 4; k++) acc[k] = make_float4(0.f, 0.f, 0.f, 0.f);
            #pragma unroll
            for (int m = 0; m < 8; m++) {
                int row = r0 + 8 * m;
                uint2 u = *(const uint2*)&epg[row * D_ + 4 * c];
                __half2* hp = (__half2*)&u;
                float2 f0 = __half22float2(hp[0]);
                float2 f1 = __half22float2(hp[1]);
                #pragma unroll
                for (int k = 0; k < 4; k++) {
                    float p = pr[q * 1024 + k * 256 + h * 64 + row];  // broadcast
                    acc[k].x += p * f0.x; acc[k].y += p * f0.y;
                    acc[k].z += p * f1.x; acc[k].w += p * f1.y;
                }
            }
            #pragma unroll
            for (int k = 0; k < 4; k++) red[(r0 * 4 + k) * 32 + c] = acc[k];
            __syncthreads();
            if (t < 128) {
                const int k = t >> 5, cc = t & 31;
                float4 s = red[k * 32 + cc];
                #pragma unroll
                for (int r = 1; r < 8; r++) {
                    float4 u = red[(r * 4 + k) * 32 + cc];
                    s.x += u.x; s.y += u.y; s.z += u.z; s.w += u.w;
                }
                *(float4*)&as[(q * 4 + k) * 512 + h * D_ + 4 * cc] = s;
            }
            __syncthreads();
        }
    }

    // MLP: 8 rows of as -> out. g = t>>7 owns rows g*4+m.
    const int d = t & 127, g = t >> 7;
    float acc[4];
    #pragma unroll
    for (int m = 0; m < 4; m++) acc[m] = 0.f;
    for (int i0 = 0; i0 < 512; i0 += 4) {
        float wv0 = w3a[(i0 + 0) * D_ + d];
        float wv1 = w3a[(i0 + 1) * D_ + d];
        float wv2 = w3a[(i0 + 2) * D_ + d];
        float wv3 = w3a[(i0 + 3) * D_ + d];
        #pragma unroll
        for (int m = 0; m < 4; m++) {
            float4 av = *(const float4*)&as[(g * 4 + m) * 512 + i0];  // broadcast
            acc[m] += av.x * wv0 + av.y * wv1 + av.z * wv2 + av.w * wv3;
        }
    }
    {
        float bb = b3a[d], gg = g3a[d], be = be3a[d];
        #pragma unroll
        for (int m = 0; m < 4; m++) {
            float v = (acc[m] + bb) * gg + be;
            h1[(g * 4 + m) * D_ + d] = fmaxf(v, 0.f);
        }
    }
    __syncthreads();

    #pragma unroll
    for (int m = 0; m < 4; m++) acc[m] = 0.f;
    for (int i0 = 0; i0 < D_; i0 += 4) {
        float wv0 = w3b[(i0 + 0) * D_ + d];
        float wv1 = w3b[(i0 + 1) * D_ + d];
        float wv2 = w3b[(i0 + 2) * D_ + d];
        float wv3 = w3b[(i0 + 3) * D_ + d];
        #pragma unroll
        for (int m = 0; m < 4; m++) {
            float4 hv = *(const float4*)&h1[(g * 4 + m) * D_ + i0];
            acc[m] += hv.x * wv0 + hv.y * wv1 + hv.z * wv2 + hv.w * wv3;
        }
    }
    {
        float bb = b3b[d], gg = g3b[d], be = be3b[d];
        #pragma unroll
        for (int m = 0; m < 4; m++) {
            float v = (acc[m] + bb) * gg + be;
            int b_out = 2 * bi + g + 1024 * m;
            out[(size_t)b_out * D_ + d] = fmaxf(v, 0.f);
        }
    }
}

// ---------------------------------------------------------------------------
extern "C" void kernel_launch(void* const* d_in, const int* in_sizes, int n_in,
                              void* d_out, int out_size) {
    const float* x    = (const float*)d_in[0];
    const float* w_q  = (const float*)d_in[1];
    const float* b_q  = (const float*)d_in[2];
    const float* w_k  = (const float*)d_in[3];
    // d_in[4] = b_k: constant over s -> cancels in softmax. Unused.
    const float* w2   = (const float*)d_in[5];
    const float* b2   = (const float*)d_in[6];
    const float* w3a  = (const float*)d_in[7];
    const float* b3a  = (const float*)d_in[8];
    const float* g3a  = (const float*)d_in[9];
    const float* be3a = (const float*)d_in[10];
    const float* w3b  = (const float*)d_in[11];
    const float* b3b  = (const float*)d_in[12];
    const float* g3b  = (const float*)d_in[13];
    const float* be3b = (const float*)d_in[14];
    float* out = (float*)d_out;

    kMeanEP  <<<B_, 256>>>(x, w_k);
    kCS      <<<B_ / 8, 256>>>(w_q, b_q, w2, b2);
    kAttnMLP <<<B_ / 8, 256>>>(w3a, b3a, g3a, be3a, w3b, b3b, g3b, be3b, out);
}

// round 11
// speedup vs baseline: 2.1647x; 1.0089x over previous
#include <cuda_runtime.h>
#include <cuda_fp16.h>
#include <math.h>

// TemporalAttentionEncoder — 2 launches.
//   kPre     : per-block (8 batches): stream x -> e_p fp16 (global) + e_mean (smem);
//              q chain (w_q, w2 coalesced; w_k rows L1-cached) -> r (smem);
//              warp-per-batch scores (stream own ep16 from L2) + softmax -> probs.
//              b_k cancels in softmax.
//   kAttnMLP : block owns sources 8bi..8bi+7 -> 8 consumers complete (all heads);
//              attn in smem, MLP fused.

#define B_   4096
#define S_   64
#define D_   128
#define H_   4

__device__ __align__(16) __half g_ep16[(size_t)B_ * S_ * D_];   // 64 MB
__device__ __align__(16) float  g_probs[(size_t)B_ * H_ * S_];  // 4 MB

// ---------------------------------------------------------------------------
// Fused mean/ep + chain + scores + softmax.  8 batches/block, 256 threads.
__global__ void __launch_bounds__(256) kPre(
    const float* __restrict__ x,
    const float* __restrict__ w_q, const float* __restrict__ b_q,
    const float* __restrict__ w2,  const float* __restrict__ b2,
    const float* __restrict__ w_k)
{
    __shared__ float chainbuf[3 * 1024];             // em | qm | qh ; aliased below
    __shared__ __align__(16) float rs[8 * H_ * D_];  // 16 KB: rs[(k*4+h)*128+d]
    float* em = chainbuf;                            // 1024 floats  (8 x 128 e_mean)
    float* qm = chainbuf + 1024;
    float* qh = chainbuf + 2048;
    float4* red = (float4*)(chainbuf + 1024);        // phase-A reduce buf (aliases qm)
    float* sc = chainbuf;                            // scores buf (aliases em/qm later)

    const int t = threadIdx.x;
    const int b0 = blockIdx.x * 8;
    const int c = t & 31, r0 = t >> 5;
    const int d = t & 127, g = t >> 7;

    // pe for this thread's (rows r0+8j, dims 4c..4c+3), computed once
    float4 pe4[8];
    {
        const float f0 = __powf(1000.0f, -(float)(2 * c) / 64.0f);
        const float f1 = __powf(1000.0f, -(float)(2 * c + 1) / 64.0f);
        #pragma unroll
        for (int j = 0; j < 8; j++) {
            float row = (float)(r0 + 8 * j);
            pe4[j] = make_float4(__sinf(row * f0), __cosf(row * f0),
                                 __sinf(row * f1), __cosf(row * f1));
        }
    }

    // ---- phase A: per batch m: e_p -> fp16 global; e_mean -> em smem ----
    #pragma unroll 1
    for (int m = 0; m < 8; m++) {
        const int b = b0 + m;
        const float4* xb = (const float4*)(x + (size_t)b * (S_ * D_));
        float4 acc = make_float4(0.f, 0.f, 0.f, 0.f);
        #pragma unroll
        for (int j = 0; j < 8; j++) {
            int row = r0 + 8 * j;
            float4 v = xb[row * 32 + c];
            v.x += pe4[j].x; v.y += pe4[j].y; v.z += pe4[j].z; v.w += pe4[j].w;
            acc.x += v.x; acc.y += v.y; acc.z += v.z; acc.w += v.w;
            __half2 h0 = __floats2half2_rn(v.x, v.y);
            __half2 h1 = __floats2half2_rn(v.z, v.w);
            uint2 u;
            u.x = *(unsigned int*)&h0;
            u.y = *(unsigned int*)&h1;
            *(uint2*)&g_ep16[((size_t)b * S_ + row) * D_ + 4 * c] = u;
        }
        red[r0 * 32 + c] = acc;
        __syncthreads();
        if (t < 32) {
            float4 s = red[t];
            #pragma unroll
            for (int r = 1; r < 8; r++) {
                float4 u = red[r * 32 + t];
                s.x += u.x; s.y += u.y; s.z += u.z; s.w += u.w;
            }
            const float inv = 1.0f / (float)S_;
            *(float4*)&em[m * D_ + 4 * t] =
                make_float4(s.x * inv, s.y * inv, s.z * inv, s.w * inv);
        }
        __syncthreads();
    }

    // ---- phase B: chain (block-cooperative over 8 batches) ----
    {
        float acc[4] = {0.f, 0.f, 0.f, 0.f};
        for (int j = 0; j < D_; j++) {
            float wv = w_q[j * D_ + d];
            #pragma unroll
            for (int m = 0; m < 4; m++) acc[m] += em[(g * 4 + m) * D_ + j] * wv;
        }
        float bq = b_q[d];
        __syncthreads();   // em reads done before qm (aliases red history) written
        #pragma unroll
        for (int m = 0; m < 4; m++) qm[(g * 4 + m) * D_ + d] = acc[m] + bq;
    }
    __syncthreads();
    {
        float acc[4] = {0.f, 0.f, 0.f, 0.f};
        for (int j = 0; j < D_; j++) {
            float wv = w2[j * D_ + d];
            #pragma unroll
            for (int m = 0; m < 4; m++) acc[m] += qm[(g * 4 + m) * D_ + j] * wv;
        }
        float bb = b2[d];
        #pragma unroll
        for (int m = 0; m < 4; m++) qh[(g * 4 + m) * D_ + d] = acc[m] + bb;
    }
    __syncthreads();
    // r[k,h,d] = sum_j w_k[d][h*32+j] * qh[k][h*32+j]  (w_k row d: L1-resident)
    #pragma unroll
    for (int h = 0; h < H_; h++) {
        float acc[4] = {0.f, 0.f, 0.f, 0.f};
        #pragma unroll
        for (int j4 = 0; j4 < 8; j4++) {
            float4 wv = *(const float4*)&w_k[d * D_ + h * 32 + j4 * 4];
            #pragma unroll
            for (int m = 0; m < 4; m++) {
                float4 qv = *(const float4*)&qh[(g * 4 + m) * D_ + h * 32 + j4 * 4];
                acc[m] += wv.x * qv.x + wv.y * qv.y + wv.z * qv.z + wv.w * qv.w;
            }
        }
        #pragma unroll
        for (int m = 0; m < 4; m++) rs[((g * 4 + m) * 4 + h) * D_ + d] = acc[m];
    }
    __syncthreads();   // rs ready; em/qm dead -> sc alias safe

    // ---- phase C: scores (warp-autonomous, batch = b0 + w) ----
    const int w = t >> 5, lane = t & 31;
    const int rg = lane >> 3, u = lane & 7;
    const __half* epg = g_ep16 + (size_t)(b0 + w) * (S_ * D_);
    const float scale = 0.17677669529663689f;  // 1/sqrt(32)

    #pragma unroll 4
    for (int iter = 0; iter < 16; iter++) {
        const int s = iter * 4 + rg;
        const __half* ebase = epg + s * D_ + u * 4;
        float acc[4] = {0.f, 0.f, 0.f, 0.f};
        #pragma unroll
        for (int k = 0; k < 4; k++) {
            uint2 uu = *(const uint2*)(ebase + 32 * k);
            __half2* hp = (__half2*)&uu;
            float2 f0 = __half22float2(hp[0]);
            float2 f1 = __half22float2(hp[1]);
            #pragma unroll
            for (int h = 0; h < 4; h++) {
                float4 rv = *(const float4*)&rs[(w * 4 + h) * D_ + u * 4 + 32 * k];
                acc[h] += f0.x * rv.x + f0.y * rv.y + f1.x * rv.z + f1.y * rv.w;
            }
        }
        #pragma unroll
        for (int o = 1; o < 8; o <<= 1) {
            #pragma unroll
            for (int h = 0; h < 4; h++)
                acc[h] += __shfl_xor_sync(0xffffffffu, acc[h], o);
        }
        if (u == 0) {
            #pragma unroll
            for (int h = 0; h < 4; h++)
                sc[w * 256 + h * 64 + s] = acc[h] * scale;
        }
    }
    __syncwarp();

    // ---- phase D: softmax (warp-local), write probs ----
    #pragma unroll
    for (int h = 0; h < 4; h++) {
        float v0 = sc[w * 256 + h * 64 + lane];
        float v1 = sc[w * 256 + h * 64 + 32 + lane];
        float mx = fmaxf(v0, v1);
        #pragma unroll
        for (int o = 16; o > 0; o >>= 1) mx = fmaxf(mx, __shfl_xor_sync(0xffffffffu, mx, o));
        float e0 = expf(v0 - mx), e1 = expf(v1 - mx);
        float sum = e0 + e1;
        #pragma unroll
        for (int o = 16; o > 0; o >>= 1) sum += __shfl_xor_sync(0xffffffffu, sum, o);
        float inv = 1.0f / sum;
        float* po = g_probs + ((size_t)(b0 + w) * H_ + h) * S_;
        po[lane] = e0 * inv;
        po[32 + lane] = e1 * inv;
    }
}

// ---------------------------------------------------------------------------
// Fused attention + MLP.  Block bi owns sources 8bi..8bi+7 (2 consumer groups),
// consumers b = 2bi+q + 1024k (q=0..1, k=0..3), ALL heads -> attn complete in
// smem, then MLP. 256 threads.
__global__ void __launch_bounds__(256) kAttnMLP(
    const float* __restrict__ w3a, const float* __restrict__ b3a,
    const float* __restrict__ g3a, const float* __restrict__ be3a,
    const float* __restrict__ w3b, const float* __restrict__ b3b,
    const float* __restrict__ g3b, const float* __restrict__ be3b,
    float* __restrict__ out)
{
    __shared__ float pr[2048];                       // 8 KB  pr[q][k][h][s]
    __shared__ __align__(16) float4 red[1024];       // 16 KB reduce buf / h1 alias
    __shared__ __align__(16) float as[8 * 512];      // 16 KB attn rows [q*4+k][512]
    float* h1 = (float*)red;

    const int t = threadIdx.x, bi = blockIdx.x;
    const int c = t & 31, r0 = t >> 5;

    #pragma unroll
    for (int z0 = 0; z0 < 8; z0++) {
        int z = t + 256 * z0;
        int q = z >> 10, k = (z >> 8) & 3, h = (z >> 6) & 3, s = z & 63;
        int b = 2 * bi + q + 1024 * k;
        pr[z] = g_probs[((size_t)b * H_ + h) * S_ + s];
    }
    __syncthreads();

    #pragma unroll
    for (int q = 0; q < 2; q++) {
        #pragma unroll
        for (int h = 0; h < H_; h++) {
            const int j = 8 * bi + 4 * q + h;
            const __half* epg = g_ep16 + (size_t)j * (S_ * D_);
            float4 acc[4];
            #pragma unroll
            for (int k = 0; k < 4; k++) acc[k] = make_float4(0.f, 0.f, 0.f, 0.f);
            #pragma unroll
            for (int m = 0; m < 8; m++) {
                int row = r0 + 8 * m;
                uint2 u = *(const uint2*)&epg[row * D_ + 4 * c];
                __half2* hp = (__half2*)&u;
                float2 f0 = __half22float2(hp[0]);
                float2 f1 = __half22float2(hp[1]);
                #pragma unroll
                for (int k = 0; k < 4; k++) {
                    float p = pr[q * 1024 + k * 256 + h * 64 + row];  // broadcast
                    acc[k].x += p * f0.x; acc[k].y += p * f0.y;
                    acc[k].z += p * f1.x; acc[k].w += p * f1.y;
                }
            }
            #pragma unroll
            for (int k = 0; k < 4; k++) red[(r0 * 4 + k) * 32 + c] = acc[k];
            __syncthreads();
            if (t < 128) {
                const int k = t >> 5, cc = t & 31;
                float4 s = red[k * 32 + cc];
                #pragma unroll
                for (int r = 1; r < 8; r++) {
                    float4 u = red[(r * 4 + k) * 32 + cc];
                    s.x += u.x; s.y += u.y; s.z += u.z; s.w += u.w;
                }
                *(float4*)&as[(q * 4 + k) * 512 + h * D_ + 4 * cc] = s;
            }
            __syncthreads();
        }
    }

    // MLP: 8 rows of as -> out. g = t>>7 owns rows g*4+m.
    const int d = t & 127, g = t >> 7;
    float acc[4];
    #pragma unroll
    for (int m = 0; m < 4; m++) acc[m] = 0.f;
    for (int i0 = 0; i0 < 512; i0 += 4) {
        float wv0 = w3a[(i0 + 0) * D_ + d];
        float wv1 = w3a[(i0 + 1) * D_ + d];
        float wv2 = w3a[(i0 + 2) * D_ + d];
        float wv3 = w3a[(i0 + 3) * D_ + d];
        #pragma unroll
        for (int m = 0; m < 4; m++) {
            float4 av = *(const float4*)&as[(g * 4 + m) * 512 + i0];  // broadcast
            acc[m] += av.x * wv0 + av.y * wv1 + av.z * wv2 + av.w * wv3;
        }
    }
    {
        float bb = b3a[d], gg = g3a[d], be = be3a[d];
        #pragma unroll
        for (int m = 0; m < 4; m++) {
            float v = (acc[m] + bb) * gg + be;
            h1[(g * 4 + m) * D_ + d] = fmaxf(v, 0.f);
        }
    }
    __syncthreads();

    #pragma unroll
    for (int m = 0; m < 4; m++) acc[m] = 0.f;
    for (int i0 = 0; i0 < D_; i0 += 4) {
        float wv0 = w3b[(i0 + 0) * D_ + d];
        float wv1 = w3b[(i0 + 1) * D_ + d];
        float wv2 = w3b[(i0 + 2) * D_ + d];
        float wv3 = w3b[(i0 + 3) * D_ + d];
        #pragma unroll
        for (int m = 0; m < 4; m++) {
            float4 hv = *(const float4*)&h1[(g * 4 + m) * D_ + i0];
            acc[m] += hv.x * wv0 + hv.y * wv1 + hv.z * wv2 + hv.w * wv3;
        }
    }
    {
        float bb = b3b[d], gg = g3b[d], be = be3b[d];
        #pragma unroll
        for (int m = 0; m < 4; m++) {
            float v = (acc[m] + bb) * gg + be;
            int b_out = 2 * bi + g + 1024 * m;
            out[(size_t)b_out * D_ + d] = fmaxf(v, 0.f);
        }
    }
}

// ---------------------------------------------------------------------------
extern "C" void kernel_launch(void* const* d_in, const int* in_sizes, int n_in,
                              void* d_out, int out_size) {
    const float* x    = (const float*)d_in[0];
    const float* w_q  = (const float*)d_in[1];
    const float* b_q  = (const float*)d_in[2];
    const float* w_k  = (const float*)d_in[3];
    // d_in[4] = b_k: constant over s -> cancels in softmax. Unused.
    const float* w2   = (const float*)d_in[5];
    const float* b2   = (const float*)d_in[6];
    const float* w3a  = (const float*)d_in[7];
    const float* b3a  = (const float*)d_in[8];
    const float* g3a  = (const float*)d_in[9];
    const float* be3a = (const float*)d_in[10];
    const float* w3b  = (const float*)d_in[11];
    const float* b3b  = (const float*)d_in[12];
    const float* g3b  = (const float*)d_in[13];
    const float* be3b = (const float*)d_in[14];
    float* out = (float*)d_out;

    kPre     <<<B_ / 8, 256>>>(x, w_q, b_q, w2, b2, w_k);
    kAttnMLP <<<B_ / 8, 256>>>(w3a, b3a, g3a, be3a, w3b, b3b, g3b, be3b, out);
}